// round 1
// baseline (speedup 1.0000x reference)
#include <cuda_runtime.h>
#include <math.h>

#define NN 10000
#define EE 160000
#define FH 256
#define PH 1024

// ---------------- scratch (device globals — no allocations allowed) --------
__device__ float g_dinv[NN];
__device__ int   g_count[NN];
__device__ int   g_fill[NN];
__device__ int   g_rowptr[NN + 1];
__device__ int   g_col[EE];
__device__ float g_ew[EE];
__device__ float g_h0[NN * FH];
__device__ float g_bufA[NN * PH];
__device__ float g_bufB[NN * PH];
__device__ float g_cat0[NN * PH];
__device__ float g_cat1[NN * PH];

__device__ __forceinline__ float gelu_f(float x) {
    return 0.5f * x * (1.0f + erff(x * 0.70710678118654752f));
}

// ---------------- graph preprocessing ---------------------------------------
__global__ void k_zero() {
    int i = blockIdx.x * blockDim.x + threadIdx.x;
    if (i < NN) { g_count[i] = 0; g_fill[i] = 0; }
}

__global__ void k_count(const int* __restrict__ ei) {
    int e = blockIdx.x * blockDim.x + threadIdx.x;
    if (e < EE) atomicAdd(&g_count[ei[EE + e]], 1);
}

__global__ void k_dinv() {
    int i = blockIdx.x * blockDim.x + threadIdx.x;
    if (i < NN) g_dinv[i] = rsqrtf((float)(g_count[i] + 1));  // +1 self-loop
}

// single-block exclusive scan of g_count -> g_rowptr
__global__ void k_scan() {
    const int T = 256;
    int tid = threadIdx.x;
    int chunk = (NN + T - 1) / T;
    int b = tid * chunk;
    int e = min(b + chunk, NN);
    int local = 0;
    for (int i = b; i < e; i++) local += g_count[i];
    __shared__ int sh[T];
    sh[tid] = local;
    __syncthreads();
    for (int off = 1; off < T; off <<= 1) {
        int v = (tid >= off) ? sh[tid - off] : 0;
        __syncthreads();
        sh[tid] += v;
        __syncthreads();
    }
    int run = sh[tid] - local;  // exclusive prefix
    for (int i = b; i < e; i++) { int c = g_count[i]; g_rowptr[i] = run; run += c; }
    if (tid == T - 1) g_rowptr[NN] = run;
}

__global__ void k_scatter(const int* __restrict__ ei) {
    int e = blockIdx.x * blockDim.x + threadIdx.x;
    if (e >= EE) return;
    int s = ei[e];
    int d = ei[EE + e];
    int pos = g_rowptr[d] + atomicAdd(&g_fill[d], 1);
    g_col[pos] = s;
    g_ew[pos]  = g_dinv[s] * g_dinv[d];
}

// ---------------- GEMM: C[n,M] = act(A[n,K] @ B[K,M] + bias), C at ldc/coff --
template <int ACT>
__global__ void k_gemm(const float* __restrict__ A, const float* __restrict__ B,
                       const float* __restrict__ bias, float* __restrict__ C,
                       int nrows, int K, int M, int ldc, int coff) {
    __shared__ float As[16][68];
    __shared__ float Bs[16][68];
    int bm = blockIdx.y * 64, bn = blockIdx.x * 64;
    int tid = threadIdx.x;
    int tx = tid & 15, ty = tid >> 4;
    int ar = tid >> 2, ak = (tid & 3) * 4;
    int br = tid >> 4, bc = (tid & 15) * 4;
    float acc[4][4];
#pragma unroll
    for (int i = 0; i < 4; i++)
#pragma unroll
        for (int j = 0; j < 4; j++) acc[i][j] = 0.f;

    int arow = bm + ar;
    for (int k0 = 0; k0 < K; k0 += 16) {
        float a0 = 0.f, a1 = 0.f, a2 = 0.f, a3 = 0.f;
        if (arow < nrows) {
            const float* ap = A + (size_t)arow * K + k0 + ak;
            if (k0 + ak + 4 <= K) {
                float4 v = *(const float4*)ap;
                a0 = v.x; a1 = v.y; a2 = v.z; a3 = v.w;
            } else {
                int rem = K - (k0 + ak);
                if (rem > 0) a0 = ap[0];
                if (rem > 1) a1 = ap[1];
                if (rem > 2) a2 = ap[2];
                if (rem > 3) a3 = ap[3];
            }
        }
        As[ak + 0][ar] = a0; As[ak + 1][ar] = a1;
        As[ak + 2][ar] = a2; As[ak + 3][ar] = a3;

        float4 bv = make_float4(0.f, 0.f, 0.f, 0.f);
        if (k0 + br < K) bv = *(const float4*)(B + (size_t)(k0 + br) * M + bn + bc);
        *(float4*)&Bs[br][bc] = bv;
        __syncthreads();

#pragma unroll
        for (int k = 0; k < 16; k++) {
            float4 av = *(const float4*)&As[k][ty * 4];
            float4 bw = *(const float4*)&Bs[k][tx * 4];
            float a[4] = {av.x, av.y, av.z, av.w};
            float bb[4] = {bw.x, bw.y, bw.z, bw.w};
#pragma unroll
            for (int i = 0; i < 4; i++)
#pragma unroll
                for (int j = 0; j < 4; j++) acc[i][j] += a[i] * bb[j];
        }
        __syncthreads();
    }
#pragma unroll
    for (int i = 0; i < 4; i++) {
        int row = bm + ty * 4 + i;
        if (row >= nrows) continue;
#pragma unroll
        for (int j = 0; j < 4; j++) {
            int col = bn + tx * 4 + j;
            if (col >= M) continue;
            float v = acc[i][j] + bias[col];
            if (ACT == 1) v = gelu_f(v);
            C[(size_t)row * ldc + coff + col] = v;
        }
    }
}

// ---------------- SpMM: out = Dinv (A+I) Dinv h  (CSR gather, no atomics) ---
__global__ void k_spmm(const float* __restrict__ h, float* __restrict__ out, int F) {
    int node = blockIdx.x;
    int f = blockIdx.y * 256 + threadIdx.x;
    int beg = g_rowptr[node], end = g_rowptr[node + 1];
    float di = g_dinv[node];
    float acc = di * di * h[(size_t)node * F + f];
    for (int e = beg; e < end; e++)
        acc += g_ew[e] * h[(size_t)g_col[e] * F + f];
    out[(size_t)node * F + f] = acc;
}

// ---------------- LayerNorm(1024) + GELU, in place ---------------------------
__global__ void k_ln(float* __restrict__ h, const float* __restrict__ g,
                     const float* __restrict__ bta) {
    int node = blockIdx.x;
    int tid = threadIdx.x;  // 256
    float* row = h + (size_t)node * 1024;
    float v[4];
    float s = 0.f, ss = 0.f;
#pragma unroll
    for (int i = 0; i < 4; i++) {
        v[i] = row[tid + i * 256];
        s += v[i];
        ss += v[i] * v[i];
    }
    __shared__ float shs[8], shss[8];
#pragma unroll
    for (int o = 16; o; o >>= 1) {
        s += __shfl_down_sync(0xffffffffu, s, o);
        ss += __shfl_down_sync(0xffffffffu, ss, o);
    }
    int w = tid >> 5, lane = tid & 31;
    if (lane == 0) { shs[w] = s; shss[w] = ss; }
    __syncthreads();
    if (w == 0) {
        s = (lane < 8) ? shs[lane] : 0.f;
        ss = (lane < 8) ? shss[lane] : 0.f;
#pragma unroll
        for (int o = 4; o; o >>= 1) {
            s += __shfl_down_sync(0xffffffffu, s, o);
            ss += __shfl_down_sync(0xffffffffu, ss, o);
        }
        if (lane == 0) { shs[0] = s; shss[0] = ss; }
    }
    __syncthreads();
    float mu = shs[0] * (1.0f / 1024.0f);
    float var = shss[0] * (1.0f / 1024.0f) - mu * mu;
    float inv = rsqrtf(var + 1e-5f);
#pragma unroll
    for (int i = 0; i < 4; i++) {
        int c = tid + i * 256;
        float t = (v[i] - mu) * inv * g[c] + bta[c];
        row[c] = gelu_f(t);
    }
}

// ---------------- final dot: out[i] = h2[i,:128] . w3 + b3 -------------------
__global__ void k_out(const float* __restrict__ h2, const float* __restrict__ w3,
                      const float* __restrict__ b3, float* __restrict__ out, int n) {
    int gw = (blockIdx.x * blockDim.x + threadIdx.x) >> 5;
    int lane = threadIdx.x & 31;
    if (gw >= n) return;
    const float* row = h2 + (size_t)gw * 128;
    float s = 0.f;
#pragma unroll
    for (int i = 0; i < 4; i++) s += row[lane + i * 32] * w3[lane + i * 32];
#pragma unroll
    for (int o = 16; o; o >>= 1) s += __shfl_down_sync(0xffffffffu, s, o);
    if (lane == 0) out[gw] = s + b3[0];
}

// ---------------- host orchestration -----------------------------------------
static float* symf(const void* s) {
    void* p = nullptr;
    cudaGetSymbolAddress(&p, s);
    return (float*)p;
}

extern "C" void kernel_launch(void* const* d_in, const int* in_sizes, int n_in,
                              void* d_out, int out_size) {
    const float* x      = (const float*)d_in[0];
    const int*   ei     = (const int*)d_in[1];
    const float* w_in   = (const float*)d_in[2];
    const float* b_in   = (const float*)d_in[3];
    const float* mh_w0  = (const float*)d_in[4];
    const float* mh_b0  = (const float*)d_in[5];
    const float* mh_w12 = (const float*)d_in[6];
    const float* mh_b12 = (const float*)d_in[7];
    const float* ln_g   = (const float*)d_in[8];
    const float* ln_b   = (const float*)d_in[9];
    const float* w1     = (const float*)d_in[10];
    const float* b1     = (const float*)d_in[11];
    const float* w2     = (const float*)d_in[12];
    const float* b2     = (const float*)d_in[13];
    const float* w3     = (const float*)d_in[14];
    const float* b3     = (const float*)d_in[15];
    float* out = (float*)d_out;

    float* h0 = symf(g_h0);
    float* bA = symf(g_bufA);
    float* bB = symf(g_bufB);
    float* c0 = symf(g_cat0);
    float* c1 = symf(g_cat1);

    // graph preprocessing (CSR by dst)
    k_zero<<<(NN + 255) / 256, 256>>>();
    k_count<<<(EE + 255) / 256, 256>>>(ei);
    k_dinv<<<(NN + 255) / 256, 256>>>();
    k_scan<<<1, 256>>>();
    k_scatter<<<(EE + 255) / 256, 256>>>(ei);

    auto GEMM = [&](const float* A, const float* B, const float* bias, float* C,
                    int K, int M, int ldc, int coff, bool act) {
        dim3 g(M / 64, (NN + 63) / 64);
        if (act) k_gemm<1><<<g, 256>>>(A, B, bias, C, NN, K, M, ldc, coff);
        else     k_gemm<0><<<g, 256>>>(A, B, bias, C, NN, K, M, ldc, coff);
    };

    // input projection
    GEMM(x, w_in, b_in, h0, 84, 256, 256, 0, true);

    auto LAYER = [&](const float* hin, int Fin, const float* W, const float* Bv,
                     float* cat, const float* lg, const float* lb) {
        size_t ws = (size_t)Fin * 256;
        dim3 sg(NN, Fin / 256);
        GEMM(hin, W, Bv, cat, Fin, 256, 1024, 0, false);
        k_spmm<<<sg, 256>>>(hin, bA, Fin);
        GEMM(bA, W + ws, Bv + 256, cat, Fin, 256, 1024, 256, false);
        k_spmm<<<sg, 256>>>(bA, bB, Fin);
        GEMM(bB, W + 2 * ws, Bv + 512, cat, Fin, 256, 1024, 512, false);
        k_spmm<<<sg, 256>>>(bB, bA, Fin);
        GEMM(bA, W + 3 * ws, Bv + 768, cat, Fin, 256, 1024, 768, false);
        k_ln<<<NN, 256>>>(cat, lg, lb);
    };

    LAYER(h0, 256, mh_w0, mh_b0, c0, ln_g, ln_b);
    LAYER(c0, 1024, mh_w12, mh_b12, c1, ln_g + 1024, ln_b + 1024);
    LAYER(c1, 1024, mh_w12 + (size_t)4 * 1024 * 256, mh_b12 + 4 * 256, c0,
          ln_g + 2048, ln_b + 2048);

    // head MLP
    GEMM(c0, w1, b1, bA, 1024, 256, 256, 0, true);
    GEMM(bA, w2, b2, bB, 256, 128, 128, 0, true);
    k_out<<<(NN * 32 + 255) / 256, 256>>>(bB, w3, b3, out, NN);
}

// round 3
// speedup vs baseline: 1.3747x; 1.3747x over previous
#include <cuda_runtime.h>
#include <cuda_bf16.h>
#include <math.h>
#include <stdint.h>

#define NN 10000
#define EE 160000
#define PADN 10112          // 79 * 128

// ---------------- scratch (device globals) ----------------------------------
__device__ float g_dinv[NN];
__device__ int   g_count[NN];
__device__ int   g_fill[NN];
__device__ int   g_rowptr[NN + 1];
__device__ int   g_col[EE];
__device__ float g_ew[EE];
__device__ float g_h0[NN * 256];
__device__ float g_cat[(size_t)NN * 1024];
__device__ float g_tmp[(size_t)NN * 1024];   // 4 slabs of NN*256
__device__ float g_u2[NN * 256];
__device__ float g_mlp[NN * 256];
__device__ float g_mlp2[NN * 128];
__device__ __nv_bfloat16 g_chi[(size_t)PADN * 1024];
__device__ __nv_bfloat16 g_clo[(size_t)PADN * 1024];
#define WTOT 2621440
__device__ __nv_bfloat16 g_wth[WTOT];
__device__ __nv_bfloat16 g_wtl[WTOT];

__device__ __forceinline__ float gelu_f(float x) {
    return 0.5f * x * (1.0f + erff(x * 0.70710678118654752f));
}

__device__ __forceinline__ uint32_t smem_u32(const void* p) {
    uint32_t a;
    asm("{ .reg .u64 t; cvta.to.shared.u64 t, %1; cvt.u32.u64 %0, t; }" : "=r"(a) : "l"(p));
    return a;
}
__device__ __forceinline__ void cp16(uint32_t dst, const void* src) {
    asm volatile("cp.async.cg.shared.global [%0], [%1], 16;" :: "r"(dst), "l"(src));
}
__device__ __forceinline__ void ldsm4(uint32_t& r0, uint32_t& r1, uint32_t& r2,
                                      uint32_t& r3, uint32_t addr) {
    asm volatile("ldmatrix.sync.aligned.m8n8.x4.shared.b16 {%0,%1,%2,%3}, [%4];"
                 : "=r"(r0), "=r"(r1), "=r"(r2), "=r"(r3) : "r"(addr));
}
__device__ __forceinline__ void mma16816(float* c, const uint32_t* a, const uint32_t* b) {
    asm volatile(
        "mma.sync.aligned.m16n8k16.row.col.f32.bf16.bf16.f32 "
        "{%0,%1,%2,%3}, {%4,%5,%6,%7}, {%8,%9}, {%0,%1,%2,%3};"
        : "+f"(c[0]), "+f"(c[1]), "+f"(c[2]), "+f"(c[3])
        : "r"(a[0]), "r"(a[1]), "r"(a[2]), "r"(a[3]), "r"(b[0]), "r"(b[1]));
}

// ---------------- graph preprocessing ---------------------------------------
__global__ void k_zero() {
    int i = blockIdx.x * blockDim.x + threadIdx.x;
    if (i < NN) { g_count[i] = 0; g_fill[i] = 0; }
}
__global__ void k_count(const int* __restrict__ ei) {
    int e = blockIdx.x * blockDim.x + threadIdx.x;
    if (e < EE) atomicAdd(&g_count[ei[EE + e]], 1);
}
__global__ void k_dinvk() {
    int i = blockIdx.x * blockDim.x + threadIdx.x;
    if (i < NN) g_dinv[i] = rsqrtf((float)(g_count[i] + 1));
}
__global__ void k_scan() {
    const int T = 256;
    int tid = threadIdx.x;
    int chunk = (NN + T - 1) / T;
    int b = tid * chunk, e = min(b + chunk, NN);
    int local = 0;
    for (int i = b; i < e; i++) local += g_count[i];
    __shared__ int sh[T];
    sh[tid] = local;
    __syncthreads();
    for (int off = 1; off < T; off <<= 1) {
        int v = (tid >= off) ? sh[tid - off] : 0;
        __syncthreads();
        sh[tid] += v;
        __syncthreads();
    }
    int run = sh[tid] - local;
    for (int i = b; i < e; i++) { int c = g_count[i]; g_rowptr[i] = run; run += c; }
    if (tid == T - 1) g_rowptr[NN] = run;
}
__global__ void k_scatter(const int* __restrict__ ei) {
    int e = blockIdx.x * blockDim.x + threadIdx.x;
    if (e >= EE) return;
    int s = ei[e], d = ei[EE + e];
    int pos = g_rowptr[d] + atomicAdd(&g_fill[d], 1);
    g_col[pos] = s;
    g_ew[pos] = g_dinv[s] * g_dinv[d];
}

// ---------------- bf16 hi/lo conversion --------------------------------------
__global__ void k_conv(const float* __restrict__ x, __nv_bfloat16* __restrict__ hi,
                       __nv_bfloat16* __restrict__ lo, int n) {
    int i = blockIdx.x * blockDim.x + threadIdx.x;
    if (i >= n) return;
    float v = x[i];
    __nv_bfloat16 h = __float2bfloat16(v);
    hi[i] = h;
    lo[i] = __float2bfloat16(v - __bfloat162float(h));
}
// W [K,256] row-major -> transposed Th/Tl [256,K]
__global__ void k_wconv(const float* __restrict__ W, __nv_bfloat16* __restrict__ th,
                        __nv_bfloat16* __restrict__ tl, int K) {
    int e = blockIdx.x * blockDim.x + threadIdx.x;
    if (e >= K * 256) return;
    int k = e >> 8, n = e & 255;
    float v = W[e];
    __nv_bfloat16 h = __float2bfloat16(v);
    size_t o = (size_t)n * K + k;
    th[o] = h;
    tl[o] = __float2bfloat16(v - __bfloat162float(h));
}

// ---------------- mma.sync bf16 GEMM -----------------------------------------
// C[PADN,256] = act(A @ Wt^T + bias); A hi/lo [PADN,K] row-major,
// Wt hi/lo [256,K] row-major. 3 passes: AhBh + AlBh + AhBl.
// Block 128x128, 8 warps (2x4), warp 64x32, BK=32, 2-stage cp.async.
__global__ void __launch_bounds__(256, 1) k_mma(
    const __nv_bfloat16* __restrict__ Ah, const __nv_bfloat16* __restrict__ Al,
    const __nv_bfloat16* __restrict__ Bh, const __nv_bfloat16* __restrict__ Bl,
    const float* __restrict__ bias, float* __restrict__ C,
    int K, int ldc, int act, int hasBias) {
    __shared__ __align__(16) char smem[2 * 16384];
    uint32_t sb = smem_u32(smem);
    int tid = threadIdx.x, wid = tid >> 5, lane = tid & 31;
    int wm = wid >> 2, wn = wid & 3;
    int bm = blockIdx.y * 128, bn = blockIdx.x * 128;

    const __nv_bfloat16* pa[3] = {Ah, Al, Ah};
    const __nv_bfloat16* pb[3] = {Bh, Bh, Bl};
    int spp = K >> 5;        // k-iters per pass
    int S = 3 * spp;

    float acc[4][4][4];
#pragma unroll
    for (int i = 0; i < 4; i++)
#pragma unroll
        for (int j = 0; j < 4; j++)
#pragma unroll
            for (int r = 0; r < 4; r++) acc[i][j][r] = 0.f;

    auto LOAD = [&](int s) {
        int buf = s & 1;
        int pass = s / spp, kq = (s % spp) << 5;
        const __nv_bfloat16* A = pa[pass];
        const __nv_bfloat16* B = pb[pass];
        uint32_t da = sb + buf * 16384;
        uint32_t db = da + 8192;
#pragma unroll
        for (int i = 0; i < 2; i++) {
            int u = tid + (i << 8);
            int row = u >> 2, c = u & 3;
            uint32_t so = row * 64 + (((c ^ ((row >> 1) & 3)) << 4));
            cp16(da + so, A + (size_t)(bm + row) * K + kq + (c << 3));
            cp16(db + so, B + (size_t)(bn + row) * K + kq + (c << 3));
        }
        asm volatile("cp.async.commit_group;");
    };

    LOAD(0);
    for (int s = 0; s < S; s++) {
        asm volatile("cp.async.wait_group 0;");
        __syncthreads();
        if (s + 1 < S) LOAD(s + 1);
        uint32_t da = sb + (s & 1) * 16384;
        uint32_t db = da + 8192;
#pragma unroll
        for (int kk = 0; kk < 2; kk++) {        // two k16 steps in BK=32
            uint32_t a[4][4], b[4][2];
#pragma unroll
            for (int mt = 0; mt < 4; mt++) {
                int row = wm * 64 + mt * 16 + (lane & 15);
                int c = (kk << 1) + (lane >> 4);
                uint32_t ad = da + row * 64 + (((c ^ ((row >> 1) & 3)) << 4));
                ldsm4(a[mt][0], a[mt][1], a[mt][2], a[mt][3], ad);
            }
#pragma unroll
            for (int np = 0; np < 2; np++) {
                int nrow = wn * 32 + np * 16 + (lane & 7) + ((lane >> 4) << 3);
                int c = (kk << 1) + ((lane >> 3) & 1);
                uint32_t bd = db + nrow * 64 + (((c ^ ((nrow >> 1) & 3)) << 4));
                ldsm4(b[np * 2][0], b[np * 2][1], b[np * 2 + 1][0], b[np * 2 + 1][1], bd);
            }
#pragma unroll
            for (int mt = 0; mt < 4; mt++)
#pragma unroll
                for (int nt = 0; nt < 4; nt++)
                    mma16816(acc[mt][nt], a[mt], b[nt]);
        }
        __syncthreads();
    }

    // epilogue: direct stores
#pragma unroll
    for (int mt = 0; mt < 4; mt++) {
#pragma unroll
        for (int nt = 0; nt < 4; nt++) {
            int r0 = bm + wm * 64 + mt * 16 + (lane >> 2);
            int col = bn + wn * 32 + nt * 8 + ((lane & 3) << 1);
            float b0 = 0.f, b1 = 0.f;
            if (hasBias) { b0 = bias[col]; b1 = bias[col + 1]; }
            float v0 = acc[mt][nt][0] + b0, v1 = acc[mt][nt][1] + b1;
            float v2 = acc[mt][nt][2] + b0, v3 = acc[mt][nt][3] + b1;
            if (act) { v0 = gelu_f(v0); v1 = gelu_f(v1); v2 = gelu_f(v2); v3 = gelu_f(v3); }
            if (r0 < NN) *(float2*)(C + (size_t)r0 * ldc + col) = make_float2(v0, v1);
            if (r0 + 8 < NN) *(float2*)(C + (size_t)(r0 + 8) * ldc + col) = make_float2(v2, v3);
        }
    }
}

// ---------------- fp32 SGEMM (small GEMMs) -----------------------------------
template <int ACT>
__global__ void k_gemm(const float* __restrict__ A, const float* __restrict__ B,
                       const float* __restrict__ bias, float* __restrict__ C,
                       int nrows, int K, int M, int ldc, int coff) {
    __shared__ float As[16][68];
    __shared__ float Bs[16][68];
    int bm = blockIdx.y * 64, bn = blockIdx.x * 64;
    int tid = threadIdx.x;
    int tx = tid & 15, ty = tid >> 4;
    int ar = tid >> 2, ak = (tid & 3) * 4;
    int br = tid >> 4, bc = (tid & 15) * 4;
    float acc[4][4];
#pragma unroll
    for (int i = 0; i < 4; i++)
#pragma unroll
        for (int j = 0; j < 4; j++) acc[i][j] = 0.f;
    int arow = bm + ar;
    for (int k0 = 0; k0 < K; k0 += 16) {
        float a0 = 0.f, a1 = 0.f, a2 = 0.f, a3 = 0.f;
        if (arow < nrows) {
            const float* ap = A + (size_t)arow * K + k0 + ak;
            if (k0 + ak + 4 <= K) {
                float4 v = *(const float4*)ap;
                a0 = v.x; a1 = v.y; a2 = v.z; a3 = v.w;
            } else {
                int rem = K - (k0 + ak);
                if (rem > 0) a0 = ap[0];
                if (rem > 1) a1 = ap[1];
                if (rem > 2) a2 = ap[2];
                if (rem > 3) a3 = ap[3];
            }
        }
        As[ak + 0][ar] = a0; As[ak + 1][ar] = a1;
        As[ak + 2][ar] = a2; As[ak + 3][ar] = a3;
        float4 bv = make_float4(0.f, 0.f, 0.f, 0.f);
        if (k0 + br < K) bv = *(const float4*)(B + (size_t)(k0 + br) * M + bn + bc);
        *(float4*)&Bs[br][bc] = bv;
        __syncthreads();
#pragma unroll
        for (int k = 0; k < 16; k++) {
            float4 av = *(const float4*)&As[k][ty * 4];
            float4 bw = *(const float4*)&Bs[k][tx * 4];
            float a[4] = {av.x, av.y, av.z, av.w};
            float bb[4] = {bw.x, bw.y, bw.z, bw.w};
#pragma unroll
            for (int i = 0; i < 4; i++)
#pragma unroll
                for (int j = 0; j < 4; j++) acc[i][j] += a[i] * bb[j];
        }
        __syncthreads();
    }
#pragma unroll
    for (int i = 0; i < 4; i++) {
        int row = bm + ty * 4 + i;
        if (row >= nrows) continue;
#pragma unroll
        for (int j = 0; j < 4; j++) {
            int col = bn + tx * 4 + j;
            if (col >= M) continue;
            float v = acc[i][j] + bias[col];
            if (ACT == 1) v = gelu_f(v);
            C[(size_t)row * ldc + coff + col] = v;
        }
    }
}

// ---------------- SpMM (256-wide slabs, up to 3 in parallel via grid.y) ------
struct SpArgs {
    const float* i0; const float* i1; const float* i2;
    float* o0; float* o1; float* o2;
    const float* bias;           // applied for y==0 only
    int ld0, ld1, ld2;
};
__global__ void k_spmm(SpArgs a) {
    int y = blockIdx.y;
    const float* in = (y == 0) ? a.i0 : (y == 1) ? a.i1 : a.i2;
    float* out = (y == 0) ? a.o0 : (y == 1) ? a.o1 : a.o2;
    int ldo = (y == 0) ? a.ld0 : (y == 1) ? a.ld1 : a.ld2;
    int node = blockIdx.x, f = threadIdx.x;
    int beg = g_rowptr[node], end = g_rowptr[node + 1];
    float di = g_dinv[node];
    float acc = di * di * in[(size_t)node * 256 + f];
    for (int e = beg; e < end; e++)
        acc += g_ew[e] * in[(size_t)g_col[e] * 256 + f];
    if (y == 0 && a.bias) acc += a.bias[f];
    out[(size_t)node * ldo + f] = acc;
}

// ---------------- LayerNorm(1024) + GELU, in place + bf16 hi/lo --------------
__global__ void k_ln(float* __restrict__ h, const float* __restrict__ g,
                     const float* __restrict__ bta, __nv_bfloat16* __restrict__ hi,
                     __nv_bfloat16* __restrict__ lo) {
    int node = blockIdx.x;
    int tid = threadIdx.x;
    float* row = h + (size_t)node * 1024;
    float v[4];
    float s = 0.f, ss = 0.f;
#pragma unroll
    for (int i = 0; i < 4; i++) {
        v[i] = row[tid + i * 256];
        s += v[i]; ss += v[i] * v[i];
    }
    __shared__ float shs[8], shss[8];
#pragma unroll
    for (int o = 16; o; o >>= 1) {
        s += __shfl_down_sync(0xffffffffu, s, o);
        ss += __shfl_down_sync(0xffffffffu, ss, o);
    }
    int w = tid >> 5, lane = tid & 31;
    if (lane == 0) { shs[w] = s; shss[w] = ss; }
    __syncthreads();
    if (w == 0) {
        s = (lane < 8) ? shs[lane] : 0.f;
        ss = (lane < 8) ? shss[lane] : 0.f;
#pragma unroll
        for (int o = 4; o; o >>= 1) {
            s += __shfl_down_sync(0xffffffffu, s, o);
            ss += __shfl_down_sync(0xffffffffu, ss, o);
        }
        if (lane == 0) { shs[0] = s; shss[0] = ss; }
    }
    __syncthreads();
    float mu = shs[0] * (1.0f / 1024.0f);
    float var = shss[0] * (1.0f / 1024.0f) - mu * mu;
    float inv = rsqrtf(var + 1e-5f);
#pragma unroll
    for (int i = 0; i < 4; i++) {
        int c = tid + i * 256;
        float t = (v[i] - mu) * inv * g[c] + bta[c];
        t = gelu_f(t);
        row[c] = t;
        size_t o = (size_t)node * 1024 + c;
        __nv_bfloat16 hb = __float2bfloat16(t);
        hi[o] = hb;
        lo[o] = __float2bfloat16(t - __bfloat162float(hb));
    }
}

// ---------------- final dot --------------------------------------------------
__global__ void k_out(const float* __restrict__ h2, const float* __restrict__ w3,
                      const float* __restrict__ b3, float* __restrict__ out, int n) {
    int gw = (blockIdx.x * blockDim.x + threadIdx.x) >> 5;
    int lane = threadIdx.x & 31;
    if (gw >= n) return;
    const float* row = h2 + (size_t)gw * 128;
    float s = 0.f;
#pragma unroll
    for (int i = 0; i < 4; i++) s += row[lane + i * 32] * w3[lane + i * 32];
#pragma unroll
    for (int o = 16; o; o >>= 1) s += __shfl_down_sync(0xffffffffu, s, o);
    if (lane == 0) out[gw] = s + b3[0];
}

// ---------------- host orchestration -----------------------------------------
template <typename T>
static T* sym(const void* s) {
    void* p = nullptr;
    cudaGetSymbolAddress(&p, s);
    return (T*)p;
}

extern "C" void kernel_launch(void* const* d_in, const int* in_sizes, int n_in,
                              void* d_out, int out_size) {
    const float* x      = (const float*)d_in[0];
    const int*   ei     = (const int*)d_in[1];
    const float* w_in   = (const float*)d_in[2];
    const float* b_in   = (const float*)d_in[3];
    const float* mh_w0  = (const float*)d_in[4];
    const float* mh_b0  = (const float*)d_in[5];
    const float* mh_w12 = (const float*)d_in[6];
    const float* mh_b12 = (const float*)d_in[7];
    const float* ln_g   = (const float*)d_in[8];
    const float* ln_b   = (const float*)d_in[9];
    const float* w1     = (const float*)d_in[10];
    const float* b1     = (const float*)d_in[11];
    const float* w2     = (const float*)d_in[12];
    const float* b2     = (const float*)d_in[13];
    const float* w3     = (const float*)d_in[14];
    const float* b3     = (const float*)d_in[15];
    float* out = (float*)d_out;

    float* h0   = sym<float>(g_h0);
    float* cat  = sym<float>(g_cat);
    float* tmp  = sym<float>(g_tmp);
    float* u2   = sym<float>(g_u2);
    float* mlp  = sym<float>(g_mlp);
    float* mlp2 = sym<float>(g_mlp2);
    __nv_bfloat16* chi = sym<__nv_bfloat16>(g_chi);
    __nv_bfloat16* clo = sym<__nv_bfloat16>(g_clo);
    __nv_bfloat16* wth = sym<__nv_bfloat16>(g_wth);
    __nv_bfloat16* wtl = sym<__nv_bfloat16>(g_wtl);

    // graph preprocessing
    k_zero<<<(NN + 255) / 256, 256>>>();
    k_count<<<(EE + 255) / 256, 256>>>(ei);
    k_dinvk<<<(NN + 255) / 256, 256>>>();
    k_scan<<<1, 256>>>();
    k_scatter<<<(EE + 255) / 256, 256>>>(ei);

    // weight conversion (transposed hi/lo bf16)
    const size_t OFF_L0 = 0, OFF_L1 = 262144, OFF_L2 = 1310720, OFF_W1 = 2359296;
    for (int p = 0; p < 4; p++)
        k_wconv<<<256, 256>>>(mh_w0 + (size_t)p * 65536, wth + OFF_L0 + p * 65536,
                              wtl + OFF_L0 + p * 65536, 256);
    for (int m = 0; m < 8; m++)
        k_wconv<<<1024, 256>>>(mh_w12 + (size_t)m * 262144, wth + OFF_L1 + (size_t)m * 262144,
                               wtl + OFF_L1 + (size_t)m * 262144, 1024);
    k_wconv<<<1024, 256>>>(w1, wth + OFF_W1, wtl + OFF_W1, 1024);

    // input projection + conv
    k_gemm<1><<<dim3(4, (NN + 63) / 64), 256>>>(x, w_in, b_in, h0, NN, 84, 256, 256, 0);
    k_conv<<<(NN * 256 + 255) / 256, 256>>>(h0, chi, clo, NN * 256);

    dim3 tcg(2, PADN / 128);
    float* t1 = tmp;
    float* t2 = tmp + (size_t)NN * 256;
    float* t3 = tmp + (size_t)2 * NN * 256;
    float* ua = tmp + (size_t)3 * NN * 256;

    auto LAYER = [&](int K, size_t woff, size_t wstride, const float* bb,
                     const float* lg, const float* lb) {
        // 4 GEMMs: p=0 direct to cat (with bias), p>=1 to tmp slabs (no bias)
        k_mma<<<tcg, 256>>>(chi, clo, wth + woff, wtl + woff, bb, cat, K, 1024, 0, 1);
        k_mma<<<tcg, 256>>>(chi, clo, wth + woff + wstride, wtl + woff + wstride,
                            nullptr, t1, K, 256, 0, 0);
        k_mma<<<tcg, 256>>>(chi, clo, wth + woff + 2 * wstride, wtl + woff + 2 * wstride,
                            nullptr, t2, K, 256, 0, 0);
        k_mma<<<tcg, 256>>>(chi, clo, wth + woff + 3 * wstride, wtl + woff + 3 * wstride,
                            nullptr, t3, K, 256, 0, 0);
        // propagation hops (bias added at final hop of each power)
        SpArgs h1{t1, t2, t3, cat + 256, ua, u2, bb + 256, 1024, 256, 256};
        k_spmm<<<dim3(NN, 3), 256>>>(h1);
        SpArgs h2a{ua, u2, nullptr, cat + 512, t1, nullptr, bb + 512, 1024, 256, 0};
        k_spmm<<<dim3(NN, 2), 256>>>(h2a);
        SpArgs h3{t1, nullptr, nullptr, cat + 768, nullptr, nullptr, bb + 768, 1024, 0, 0};
        k_spmm<<<dim3(NN, 1), 256>>>(h3);
        k_ln<<<NN, 256>>>(cat, lg, lb, chi, clo);
    };

    LAYER(256,  OFF_L0, 65536,  mh_b0,         ln_g,        ln_b);
    LAYER(1024, OFF_L1, 262144, mh_b12,        ln_g + 1024, ln_b + 1024);
    LAYER(1024, OFF_L2, 262144, mh_b12 + 1024, ln_g + 2048, ln_b + 2048);

    // head MLP
    k_mma<<<tcg, 256>>>(chi, clo, wth + OFF_W1, wtl + OFF_W1, b1, mlp, 1024, 256, 1, 1);
    k_gemm<1><<<dim3(2, (NN + 63) / 64), 256>>>(mlp, w2, b2, mlp2, NN, 256, 128, 128, 0);
    k_out<<<(NN * 32 + 255) / 256, 256>>>(mlp2, w3, b3, out, NN);
}

// round 4
// speedup vs baseline: 2.8471x; 2.0711x over previous
#include <cuda_runtime.h>
#include <cuda_bf16.h>
#include <math.h>
#include <stdint.h>

#define NN 10000
#define EE 160000

// ---------------- scratch (device globals) ----------------------------------
__device__ float g_dinv[NN];
__device__ int   g_count[NN];
__device__ int   g_fill[NN];
__device__ int   g_rowptr[NN + 1];
__device__ int   g_col[EE];
__device__ float g_ew[EE];
__device__ float g_h0[NN * 256];
__device__ float g_cat[(size_t)NN * 1024];
__device__ float g_tmp[(size_t)NN * 1024];   // slabs t1,t2,t3,ua (NN*256 each)
__device__ float g_u2[NN * 256];
__device__ float g_mlp[NN * 256];
__device__ float g_mlp2[NN * 128];
__device__ float g_af[(size_t)NN * 1024];    // tf32-rounded GEMM input
#define WTOT 2621440
__device__ float g_wt[WTOT];                 // tf32-rounded transposed weights

__device__ __forceinline__ float gelu_f(float x) {
    return 0.5f * x * (1.0f + erff(x * 0.70710678118654752f));
}
__device__ __forceinline__ float tf32r(float x) {
    float r;
    asm("cvt.rna.tf32.f32 %0, %1;" : "=f"(r) : "f"(x));
    return r;
}
__device__ __forceinline__ uint32_t smem_u32(const void* p) {
    uint32_t a;
    asm("{ .reg .u64 t; cvta.to.shared.u64 t, %1; cvt.u32.u64 %0, t; }" : "=r"(a) : "l"(p));
    return a;
}
__device__ __forceinline__ void ldsm4(uint32_t& r0, uint32_t& r1, uint32_t& r2,
                                      uint32_t& r3, uint32_t addr) {
    asm volatile("ldmatrix.sync.aligned.m8n8.x4.shared.b16 {%0,%1,%2,%3}, [%4];"
                 : "=r"(r0), "=r"(r1), "=r"(r2), "=r"(r3) : "r"(addr));
}
__device__ __forceinline__ void mma_tf32(float* c, const uint32_t* a, const uint32_t* b) {
    asm volatile(
        "mma.sync.aligned.m16n8k8.row.col.f32.tf32.tf32.f32 "
        "{%0,%1,%2,%3}, {%4,%5,%6,%7}, {%8,%9}, {%0,%1,%2,%3};"
        : "+f"(c[0]), "+f"(c[1]), "+f"(c[2]), "+f"(c[3])
        : "r"(a[0]), "r"(a[1]), "r"(a[2]), "r"(a[3]), "r"(b[0]), "r"(b[1]));
}

// ---------------- graph preprocessing ---------------------------------------
__global__ void k_zero() {
    int i = blockIdx.x * blockDim.x + threadIdx.x;
    if (i < NN) { g_count[i] = 0; g_fill[i] = 0; }
}
__global__ void k_count(const int* __restrict__ ei) {
    int e = blockIdx.x * blockDim.x + threadIdx.x;
    if (e < EE) atomicAdd(&g_count[ei[EE + e]], 1);
}
__global__ void k_dinvk() {
    int i = blockIdx.x * blockDim.x + threadIdx.x;
    if (i < NN) g_dinv[i] = rsqrtf((float)(g_count[i] + 1));
}
__global__ void k_scan() {
    const int T = 256;
    int tid = threadIdx.x;
    int chunk = (NN + T - 1) / T;
    int b = tid * chunk, e = min(b + chunk, NN);
    int local = 0;
    for (int i = b; i < e; i++) local += g_count[i];
    __shared__ int sh[T];
    sh[tid] = local;
    __syncthreads();
    for (int off = 1; off < T; off <<= 1) {
        int v = (tid >= off) ? sh[tid - off] : 0;
        __syncthreads();
        sh[tid] += v;
        __syncthreads();
    }
    int run = sh[tid] - local;
    for (int i = b; i < e; i++) { int c = g_count[i]; g_rowptr[i] = run; run += c; }
    if (tid == T - 1) g_rowptr[NN] = run;
}
__global__ void k_scatter(const int* __restrict__ ei) {
    int e = blockIdx.x * blockDim.x + threadIdx.x;
    if (e >= EE) return;
    int s = ei[e], d = ei[EE + e];
    int pos = g_rowptr[d] + atomicAdd(&g_fill[d], 1);
    g_col[pos] = s;
    g_ew[pos] = g_dinv[s] * g_dinv[d];
}

// ---------------- conversions (tf32 rounding) --------------------------------
__global__ void k_conv(const float* __restrict__ x, float* __restrict__ o, int n) {
    int i = blockIdx.x * blockDim.x + threadIdx.x;
    if (i < n) o[i] = tf32r(x[i]);
}
// matrix m of src: [K,256] row-major -> dst rows [m*256 .. ), [n][k], tf32-rounded
__global__ void k_wconv(const float* __restrict__ src, float* __restrict__ dst,
                        int K, size_t srcStride, size_t dstStride) {
    int m = blockIdx.y;
    int e = blockIdx.x * 256 + threadIdx.x;
    if (e >= K * 256) return;
    int k = e >> 8, n = e & 255;
    dst[m * dstStride + (size_t)n * K + k] = tf32r(src[m * srcStride + e]);
}

// ---------------- tf32 mma GEMM ----------------------------------------------
// C = A[NN,K] @ Wt[N,K]^T ; block 128x128, 4 warps (2x2, 64x64 each),
// BK=32, 3-stage cp.async. Output range per 256 cols -> separate dest.
struct GOut {
    float* p[4];
    const float* b[4];
    int ld[4];
    int act;
};

__global__ void __launch_bounds__(128, 2) k_mma(
    const float* __restrict__ A, const float* __restrict__ B, GOut o, int K) {
    extern __shared__ char smc[];
    uint32_t sb = smem_u32(smc);
    int tid = threadIdx.x, lane = tid & 31, wid = tid >> 5;
    int WM = wid >> 1, WN = wid & 1;
    int bm = blockIdx.y * 128, bn = blockIdx.x * 128;
    const int NIT = K >> 5;

    float acc[4][8][4];
#pragma unroll
    for (int i = 0; i < 4; i++)
#pragma unroll
        for (int j = 0; j < 8; j++)
#pragma unroll
            for (int r = 0; r < 4; r++) acc[i][j][r] = 0.f;

    auto LOAD = [&](int it) {
        int st = it % 3;
        uint32_t da = sb + st * 32768;
        uint32_t db = da + 16384;
        int k0 = it << 5;
#pragma unroll
        for (int i = 0; i < 8; i++) {
            int idx = i * 128 + tid;
            int row = idx >> 3, c = idx & 7;
            uint32_t so = row * 128 + ((c ^ (row & 7)) << 4);
            int ar = bm + row;
            const float* as = A + (size_t)min(ar, NN - 1) * K + k0 + c * 4;
            int sz = (ar < NN) ? 16 : 0;
            asm volatile("cp.async.cg.shared.global [%0], [%1], 16, %2;"
                         :: "r"(da + so), "l"(as), "r"(sz));
            const float* bs = B + (size_t)(bn + row) * K + k0 + c * 4;
            asm volatile("cp.async.cg.shared.global [%0], [%1], 16;"
                         :: "r"(db + so), "l"(bs));
        }
        asm volatile("cp.async.commit_group;");
    };

    LOAD(0);
    LOAD(1);
    for (int it = 0; it < NIT; it++) {
        asm volatile("cp.async.wait_group 1;");
        __syncthreads();
        if (it + 2 < NIT) LOAD(it + 2);
        int st = it % 3;
        uint32_t da = sb + st * 32768, db = da + 16384;
#pragma unroll
        for (int kk = 0; kk < 4; kk++) {
            uint32_t a[4][4], b[8][2];
#pragma unroll
            for (int mt = 0; mt < 4; mt++) {
                int row = WM * 64 + mt * 16 + (lane & 15);
                int ch = kk * 2 + (lane >> 4);
                uint32_t ad = da + row * 128 + ((ch ^ (row & 7)) << 4);
                ldsm4(a[mt][0], a[mt][1], a[mt][2], a[mt][3], ad);
            }
#pragma unroll
            for (int ng = 0; ng < 4; ng++) {
                int row = WN * 64 + ng * 16 + (lane & 7) + ((lane & 16) >> 1);
                int ch = kk * 2 + ((lane >> 3) & 1);
                uint32_t bd = db + row * 128 + ((ch ^ (row & 7)) << 4);
                ldsm4(b[2 * ng][0], b[2 * ng][1], b[2 * ng + 1][0], b[2 * ng + 1][1], bd);
            }
#pragma unroll
            for (int mt = 0; mt < 4; mt++)
#pragma unroll
                for (int nt = 0; nt < 8; nt++)
                    mma_tf32(acc[mt][nt], a[mt], b[nt]);
        }
    }

    // epilogue
    int range = bn >> 8;
    float* D = o.p[range];
    const float* bias = o.b[range];
    int ldd = o.ld[range];
    int act = o.act;
#pragma unroll
    for (int mt = 0; mt < 4; mt++) {
        int r = bm + WM * 64 + mt * 16 + (lane >> 2);
#pragma unroll
        for (int nt = 0; nt < 8; nt++) {
            int gcol = (bn & 255) + WN * 64 + nt * 8 + ((lane & 3) << 1);
            float b0 = 0.f, b1 = 0.f;
            if (bias) { b0 = bias[gcol]; b1 = bias[gcol + 1]; }
            float v0 = acc[mt][nt][0] + b0, v1 = acc[mt][nt][1] + b1;
            float v2 = acc[mt][nt][2] + b0, v3 = acc[mt][nt][3] + b1;
            if (act) { v0 = gelu_f(v0); v1 = gelu_f(v1); v2 = gelu_f(v2); v3 = gelu_f(v3); }
            if (r < NN) *(float2*)(D + (size_t)r * ldd + gcol) = make_float2(v0, v1);
            if (r + 8 < NN) *(float2*)(D + (size_t)(r + 8) * ldd + gcol) = make_float2(v2, v3);
        }
    }
}

// ---------------- fp32 SGEMM (small GEMMs) -----------------------------------
template <int ACT>
__global__ void k_gemm(const float* __restrict__ A, const float* __restrict__ B,
                       const float* __restrict__ bias, float* __restrict__ C,
                       int nrows, int K, int M, int ldc, int coff) {
    __shared__ float As[16][68];
    __shared__ float Bs[16][68];
    int bm = blockIdx.y * 64, bn = blockIdx.x * 64;
    int tid = threadIdx.x;
    int tx = tid & 15, ty = tid >> 4;
    int ar = tid >> 2, ak = (tid & 3) * 4;
    int br = tid >> 4, bc = (tid & 15) * 4;
    float acc[4][4];
#pragma unroll
    for (int i = 0; i < 4; i++)
#pragma unroll
        for (int j = 0; j < 4; j++) acc[i][j] = 0.f;
    int arow = bm + ar;
    for (int k0 = 0; k0 < K; k0 += 16) {
        float a0 = 0.f, a1 = 0.f, a2 = 0.f, a3 = 0.f;
        if (arow < nrows) {
            const float* ap = A + (size_t)arow * K + k0 + ak;
            if (k0 + ak + 4 <= K) {
                float4 v = *(const float4*)ap;
                a0 = v.x; a1 = v.y; a2 = v.z; a3 = v.w;
            } else {
                int rem = K - (k0 + ak);
                if (rem > 0) a0 = ap[0];
                if (rem > 1) a1 = ap[1];
                if (rem > 2) a2 = ap[2];
                if (rem > 3) a3 = ap[3];
            }
        }
        As[ak + 0][ar] = a0; As[ak + 1][ar] = a1;
        As[ak + 2][ar] = a2; As[ak + 3][ar] = a3;
        float4 bv = make_float4(0.f, 0.f, 0.f, 0.f);
        if (k0 + br < K) bv = *(const float4*)(B + (size_t)(k0 + br) * M + bn + bc);
        *(float4*)&Bs[br][bc] = bv;
        __syncthreads();
#pragma unroll
        for (int k = 0; k < 16; k++) {
            float4 av = *(const float4*)&As[k][ty * 4];
            float4 bw = *(const float4*)&Bs[k][tx * 4];
            float a[4] = {av.x, av.y, av.z, av.w};
            float bb[4] = {bw.x, bw.y, bw.z, bw.w};
#pragma unroll
            for (int i = 0; i < 4; i++)
#pragma unroll
                for (int j = 0; j < 4; j++) acc[i][j] += a[i] * bb[j];
        }
        __syncthreads();
    }
#pragma unroll
    for (int i = 0; i < 4; i++) {
        int row = bm + ty * 4 + i;
        if (row >= nrows) continue;
#pragma unroll
        for (int j = 0; j < 4; j++) {
            int col = bn + tx * 4 + j;
            if (col >= M) continue;
            float v = acc[i][j] + bias[col];
            if (ACT == 1) v = gelu_f(v);
            C[(size_t)row * ldc + coff + col] = v;
        }
    }
}

// ---------------- SpMM (256-wide slabs, up to 3 in parallel via grid.y) ------
struct SpArgs {
    const float* i0; const float* i1; const float* i2;
    float* o0; float* o1; float* o2;
    const float* bias;           // applied for y==0 only
    int ld0, ld1, ld2;
};
__global__ void k_spmm(SpArgs a) {
    int y = blockIdx.y;
    const float* in = (y == 0) ? a.i0 : (y == 1) ? a.i1 : a.i2;
    float* out = (y == 0) ? a.o0 : (y == 1) ? a.o1 : a.o2;
    int ldo = (y == 0) ? a.ld0 : (y == 1) ? a.ld1 : a.ld2;
    int node = blockIdx.x, f = threadIdx.x;
    int beg = g_rowptr[node], end = g_rowptr[node + 1];
    float di = g_dinv[node];
    float acc = di * di * in[(size_t)node * 256 + f];
    for (int e = beg; e < end; e++)
        acc += g_ew[e] * in[(size_t)g_col[e] * 256 + f];
    if (y == 0 && a.bias) acc += a.bias[f];
    out[(size_t)node * ldo + f] = acc;
}

// ---------------- LayerNorm(1024) + GELU -> tf32-rounded g_af ----------------
__global__ void k_ln(const float* __restrict__ h, const float* __restrict__ g,
                     const float* __restrict__ bta, float* __restrict__ af) {
    int node = blockIdx.x;
    int tid = threadIdx.x;
    const float* row = h + (size_t)node * 1024;
    float v[4];
    float s = 0.f, ss = 0.f;
#pragma unroll
    for (int i = 0; i < 4; i++) {
        v[i] = row[tid + i * 256];
        s += v[i]; ss += v[i] * v[i];
    }
    __shared__ float shs[8], shss[8];
#pragma unroll
    for (int o = 16; o; o >>= 1) {
        s += __shfl_down_sync(0xffffffffu, s, o);
        ss += __shfl_down_sync(0xffffffffu, ss, o);
    }
    int w = tid >> 5, lane = tid & 31;
    if (lane == 0) { shs[w] = s; shss[w] = ss; }
    __syncthreads();
    if (w == 0) {
        s = (lane < 8) ? shs[lane] : 0.f;
        ss = (lane < 8) ? shss[lane] : 0.f;
#pragma unroll
        for (int o = 4; o; o >>= 1) {
            s += __shfl_down_sync(0xffffffffu, s, o);
            ss += __shfl_down_sync(0xffffffffu, ss, o);
        }
        if (lane == 0) { shs[0] = s; shss[0] = ss; }
    }
    __syncthreads();
    float mu = shs[0] * (1.0f / 1024.0f);
    float var = shss[0] * (1.0f / 1024.0f) - mu * mu;
    float inv = rsqrtf(var + 1e-5f);
#pragma unroll
    for (int i = 0; i < 4; i++) {
        int c = tid + i * 256;
        float t = (v[i] - mu) * inv * g[c] + bta[c];
        af[(size_t)node * 1024 + c] = tf32r(gelu_f(t));
    }
}

// ---------------- final dot --------------------------------------------------
__global__ void k_out(const float* __restrict__ h2, const float* __restrict__ w3,
                      const float* __restrict__ b3, float* __restrict__ out, int n) {
    int gw = (blockIdx.x * blockDim.x + threadIdx.x) >> 5;
    int lane = threadIdx.x & 31;
    if (gw >= n) return;
    const float* row = h2 + (size_t)gw * 128;
    float s = 0.f;
#pragma unroll
    for (int i = 0; i < 4; i++) s += row[lane + i * 32] * w3[lane + i * 32];
#pragma unroll
    for (int o = 16; o; o >>= 1) s += __shfl_down_sync(0xffffffffu, s, o);
    if (lane == 0) out[gw] = s + b3[0];
}

// ---------------- host orchestration -----------------------------------------
template <typename T>
static T* sym(const void* s) {
    void* p = nullptr;
    cudaGetSymbolAddress(&p, s);
    return (T*)p;
}

extern "C" void kernel_launch(void* const* d_in, const int* in_sizes, int n_in,
                              void* d_out, int out_size) {
    const float* x      = (const float*)d_in[0];
    const int*   ei     = (const int*)d_in[1];
    const float* w_in   = (const float*)d_in[2];
    const float* b_in   = (const float*)d_in[3];
    const float* mh_w0  = (const float*)d_in[4];
    const float* mh_b0  = (const float*)d_in[5];
    const float* mh_w12 = (const float*)d_in[6];
    const float* mh_b12 = (const float*)d_in[7];
    const float* ln_g   = (const float*)d_in[8];
    const float* ln_b   = (const float*)d_in[9];
    const float* w1     = (const float*)d_in[10];
    const float* b1     = (const float*)d_in[11];
    const float* w2     = (const float*)d_in[12];
    const float* b2     = (const float*)d_in[13];
    const float* w3     = (const float*)d_in[14];
    const float* b3     = (const float*)d_in[15];
    float* out = (float*)d_out;

    float* h0   = sym<float>(g_h0);
    float* cat  = sym<float>(g_cat);
    float* tmp  = sym<float>(g_tmp);
    float* u2   = sym<float>(g_u2);
    float* mlp  = sym<float>(g_mlp);
    float* mlp2 = sym<float>(g_mlp2);
    float* af   = sym<float>(g_af);
    float* wt   = sym<float>(g_wt);

    static bool attr_done = false;
    if (!attr_done) {
        cudaFuncSetAttribute(k_mma, cudaFuncAttributeMaxDynamicSharedMemorySize, 98304);
        attr_done = true;
    }

    // graph preprocessing
    k_zero<<<(NN + 255) / 256, 256>>>();
    k_count<<<(EE + 255) / 256, 256>>>(ei);
    k_dinvk<<<(NN + 255) / 256, 256>>>();
    k_scan<<<1, 256>>>();
    k_scatter<<<(EE + 255) / 256, 256>>>(ei);

    // weight conversion (transposed, tf32-rounded)
    const size_t OFF_L0 = 0, OFF_L1 = 262144, OFF_W1 = 2359296;
    k_wconv<<<dim3(256, 4), 256>>>(mh_w0, wt + OFF_L0, 256, 65536, 65536);
    k_wconv<<<dim3(1024, 8), 256>>>(mh_w12, wt + OFF_L1, 1024, 262144, 262144);
    k_wconv<<<dim3(1024, 1), 256>>>(w1, wt + OFF_W1, 1024, 262144, 262144);

    // input projection + round
    k_gemm<1><<<dim3(4, (NN + 63) / 64), 256>>>(x, w_in, b_in, h0, NN, 84, 256, 256, 0);
    k_conv<<<(NN * 256 + 255) / 256, 256>>>(h0, af, NN * 256);

    float* t1 = tmp;
    float* t2 = tmp + (size_t)NN * 256;
    float* t3 = tmp + (size_t)2 * NN * 256;
    float* ua = tmp + (size_t)3 * NN * 256;

    auto LAYER = [&](int K, size_t woff, const float* bb,
                     const float* lg, const float* lb) {
        GOut o;
        o.p[0] = cat; o.p[1] = t1; o.p[2] = t2; o.p[3] = t3;
        o.b[0] = bb;  o.b[1] = nullptr; o.b[2] = nullptr; o.b[3] = nullptr;
        o.ld[0] = 1024; o.ld[1] = 256; o.ld[2] = 256; o.ld[3] = 256;
        o.act = 0;
        k_mma<<<dim3(8, 79), 128, 98304>>>(af, wt + woff, o, K);
        SpArgs h1{t1, t2, t3, cat + 256, ua, u2, bb + 256, 1024, 256, 256};
        k_spmm<<<dim3(NN, 3), 256>>>(h1);
        SpArgs h2a{ua, u2, nullptr, cat + 512, t1, nullptr, bb + 512, 1024, 256, 0};
        k_spmm<<<dim3(NN, 2), 256>>>(h2a);
        SpArgs h3{t1, nullptr, nullptr, cat + 768, nullptr, nullptr, bb + 768, 1024, 0, 0};
        k_spmm<<<dim3(NN, 1), 256>>>(h3);
        k_ln<<<NN, 256>>>(cat, lg, lb, af);
    };

    LAYER(256,  OFF_L0,                mh_b0,         ln_g,        ln_b);
    LAYER(1024, OFF_L1,                mh_b12,        ln_g + 1024, ln_b + 1024);
    LAYER(1024, OFF_L1 + 4 * 262144,   mh_b12 + 1024, ln_g + 2048, ln_b + 2048);

    // head MLP
    GOut oh;
    oh.p[0] = mlp; oh.p[1] = nullptr; oh.p[2] = nullptr; oh.p[3] = nullptr;
    oh.b[0] = b1;  oh.b[1] = nullptr; oh.b[2] = nullptr; oh.b[3] = nullptr;
    oh.ld[0] = 256; oh.ld[1] = 0; oh.ld[2] = 0; oh.ld[3] = 0;
    oh.act = 1;
    k_mma<<<dim3(2, 79), 128, 98304>>>(af, wt + OFF_W1, oh, 1024);
    k_gemm<1><<<dim3(2, (NN + 63) / 64), 256>>>(mlp, w2, b2, mlp2, NN, 256, 128, 128, 0);
    k_out<<<(NN * 32 + 255) / 256, 256>>>(mlp2, w3, b3, out, NN);
}

// round 5
// speedup vs baseline: 3.6747x; 1.2907x over previous
#include <cuda_runtime.h>
#include <cuda_bf16.h>
#include <math.h>
#include <stdint.h>

#define NN 10000
#define EE 160000

// ---------------- scratch (device globals) ----------------------------------
__device__ float g_dinv[NN];
__device__ int   g_count[NN];
__device__ int   g_fill[NN];
__device__ int   g_rowptr[NN + 1];
__device__ int   g_col[EE];
__device__ float g_ew[EE];
__device__ float g_cat[(size_t)NN * 1024];
__device__ float g_tmp[(size_t)NN * 1024];   // slabs t1,t2,t3,ua (NN*256 each)
__device__ float g_u2[NN * 256];
__device__ float g_mlp[NN * 256];
__device__ float g_mlp2[NN * 128];
__device__ float g_af[(size_t)NN * 1024];    // tf32-rounded GEMM input
#define WTOT 2654208
__device__ float g_wt[WTOT];                 // tf32-rounded transposed weights

__device__ __forceinline__ float gelu_f(float x) {
    return 0.5f * x * (1.0f + erff(x * 0.70710678118654752f));
}
__device__ __forceinline__ float tf32r(float x) {
    float r;
    asm("cvt.rna.tf32.f32 %0, %1;" : "=f"(r) : "f"(x));
    return r;
}
__device__ __forceinline__ uint32_t smem_u32(const void* p) {
    uint32_t a;
    asm("{ .reg .u64 t; cvta.to.shared.u64 t, %1; cvt.u32.u64 %0, t; }" : "=r"(a) : "l"(p));
    return a;
}
__device__ __forceinline__ void ldsm4(uint32_t& r0, uint32_t& r1, uint32_t& r2,
                                      uint32_t& r3, uint32_t addr) {
    asm volatile("ldmatrix.sync.aligned.m8n8.x4.shared.b16 {%0,%1,%2,%3}, [%4];"
                 : "=r"(r0), "=r"(r1), "=r"(r2), "=r"(r3) : "r"(addr));
}
__device__ __forceinline__ void mma_tf32(float* c, const uint32_t* a, const uint32_t* b) {
    asm volatile(
        "mma.sync.aligned.m16n8k8.row.col.f32.tf32.tf32.f32 "
        "{%0,%1,%2,%3}, {%4,%5,%6,%7}, {%8,%9}, {%0,%1,%2,%3};"
        : "+f"(c[0]), "+f"(c[1]), "+f"(c[2]), "+f"(c[3])
        : "r"(a[0]), "r"(a[1]), "r"(a[2]), "r"(a[3]), "r"(b[0]), "r"(b[1]));
}

// ---------------- graph preprocessing ---------------------------------------
__global__ void k_zero() {
    int i = blockIdx.x * blockDim.x + threadIdx.x;
    if (i < NN) { g_count[i] = 0; g_fill[i] = 0; }
}
__global__ void k_count(const int* __restrict__ ei) {
    int e = blockIdx.x * blockDim.x + threadIdx.x;
    if (e < EE) atomicAdd(&g_count[ei[EE + e]], 1);
}
__global__ void k_dinvk() {
    int i = blockIdx.x * blockDim.x + threadIdx.x;
    if (i < NN) g_dinv[i] = rsqrtf((float)(g_count[i] + 1));
}
__global__ void k_scan() {
    const int T = 1024;
    int tid = threadIdx.x;
    int chunk = (NN + T - 1) / T;   // 10
    int b = tid * chunk, e = min(b + chunk, NN);
    int local = 0;
    for (int i = b; i < e; i++) local += g_count[i];
    __shared__ int sh[T];
    sh[tid] = local;
    __syncthreads();
    for (int off = 1; off < T; off <<= 1) {
        int v = (tid >= off) ? sh[tid - off] : 0;
        __syncthreads();
        sh[tid] += v;
        __syncthreads();
    }
    int run = sh[tid] - local;
    for (int i = b; i < e; i++) { int c = g_count[i]; g_rowptr[i] = run; run += c; }
    if (tid == T - 1) g_rowptr[NN] = run;
}
__global__ void k_scatter(const int* __restrict__ ei) {
    int e = blockIdx.x * blockDim.x + threadIdx.x;
    if (e >= EE) return;
    int s = ei[e], d = ei[EE + e];
    int pos = g_rowptr[d] + atomicAdd(&g_fill[d], 1);
    g_col[pos] = s;
    g_ew[pos] = g_dinv[s] * g_dinv[d];
}

// ---------------- weight conversion (transposed, tf32-rounded) ---------------
// matrix m of src: [K,N] row-major -> dst + m*dstStride as [N][K]
__global__ void k_wconv(const float* __restrict__ src, float* __restrict__ dst,
                        int K, int N, size_t srcStride, size_t dstStride) {
    int m = blockIdx.y;
    int e = blockIdx.x * 256 + threadIdx.x;
    if (e >= K * N) return;
    int k = e / N, n = e % N;
    dst[m * dstStride + (size_t)n * K + k] = tf32r(src[m * srcStride + e]);
}

// ---------------- tf32 mma GEMM ----------------------------------------------
// C = A[NN,K] @ Wt[N,K]^T ; block 128x128, 4 warps (2x2, 64x64 each),
// BK=32, 3-stage cp.async. Output range per 256 cols -> separate dest.
// act: 0=none, 1=gelu, 2=gelu+tf32 round
struct GOut {
    float* p[4];
    const float* b[4];
    int ld[4];
    int act;
};

__global__ void __launch_bounds__(128, 2) k_mma(
    const float* __restrict__ A, const float* __restrict__ B, GOut o, int K) {
    extern __shared__ char smc[];
    uint32_t sb = smem_u32(smc);
    int tid = threadIdx.x, lane = tid & 31, wid = tid >> 5;
    int WM = wid >> 1, WN = wid & 1;
    int bm = blockIdx.y * 128, bn = blockIdx.x * 128;
    const int NIT = K >> 5;

    float acc[4][8][4];
#pragma unroll
    for (int i = 0; i < 4; i++)
#pragma unroll
        for (int j = 0; j < 8; j++)
#pragma unroll
            for (int r = 0; r < 4; r++) acc[i][j][r] = 0.f;

    auto LOAD = [&](int it) {
        int st = it % 3;
        uint32_t da = sb + st * 32768;
        uint32_t db = da + 16384;
        int k0 = it << 5;
#pragma unroll
        for (int i = 0; i < 8; i++) {
            int idx = i * 128 + tid;
            int row = idx >> 3, c = idx & 7;
            uint32_t so = row * 128 + ((c ^ (row & 7)) << 4);
            int ar = bm + row;
            const float* as = A + (size_t)min(ar, NN - 1) * K + k0 + c * 4;
            int sz = (ar < NN) ? 16 : 0;
            asm volatile("cp.async.cg.shared.global [%0], [%1], 16, %2;"
                         :: "r"(da + so), "l"(as), "r"(sz));
            const float* bs = B + (size_t)(bn + row) * K + k0 + c * 4;
            asm volatile("cp.async.cg.shared.global [%0], [%1], 16;"
                         :: "r"(db + so), "l"(bs));
        }
        asm volatile("cp.async.commit_group;");
    };

    LOAD(0);
    LOAD(1);
    for (int it = 0; it < NIT; it++) {
        asm volatile("cp.async.wait_group 1;");
        __syncthreads();
        if (it + 2 < NIT) LOAD(it + 2);
        int st = it % 3;
        uint32_t da = sb + st * 32768, db = da + 16384;
#pragma unroll
        for (int kk = 0; kk < 4; kk++) {
            uint32_t a[4][4], b[8][2];
#pragma unroll
            for (int mt = 0; mt < 4; mt++) {
                int row = WM * 64 + mt * 16 + (lane & 15);
                int ch = kk * 2 + (lane >> 4);
                uint32_t ad = da + row * 128 + ((ch ^ (row & 7)) << 4);
                ldsm4(a[mt][0], a[mt][1], a[mt][2], a[mt][3], ad);
            }
#pragma unroll
            for (int ng = 0; ng < 4; ng++) {
                int row = WN * 64 + ng * 16 + (lane & 7) + ((lane & 16) >> 1);
                int ch = kk * 2 + ((lane >> 3) & 1);
                uint32_t bd = db + row * 128 + ((ch ^ (row & 7)) << 4);
                ldsm4(b[2 * ng][0], b[2 * ng][1], b[2 * ng + 1][0], b[2 * ng + 1][1], bd);
            }
#pragma unroll
            for (int mt = 0; mt < 4; mt++)
#pragma unroll
                for (int nt = 0; nt < 8; nt++)
                    mma_tf32(acc[mt][nt], a[mt], b[nt]);
        }
    }

    // epilogue
    int range = bn >> 8;
    float* D = o.p[range];
    const float* bias = o.b[range];
    int ldd = o.ld[range];
    int act = o.act;
#pragma unroll
    for (int mt = 0; mt < 4; mt++) {
        int r = bm + WM * 64 + mt * 16 + (lane >> 2);
#pragma unroll
        for (int nt = 0; nt < 8; nt++) {
            int gcol = (bn & 255) + WN * 64 + nt * 8 + ((lane & 3) << 1);
            float b0 = 0.f, b1 = 0.f;
            if (bias) { b0 = bias[gcol]; b1 = bias[gcol + 1]; }
            float v0 = acc[mt][nt][0] + b0, v1 = acc[mt][nt][1] + b1;
            float v2 = acc[mt][nt][2] + b0, v3 = acc[mt][nt][3] + b1;
            if (act) {
                v0 = gelu_f(v0); v1 = gelu_f(v1); v2 = gelu_f(v2); v3 = gelu_f(v3);
                if (act == 2) { v0 = tf32r(v0); v1 = tf32r(v1); v2 = tf32r(v2); v3 = tf32r(v3); }
            }
            if (r < NN) *(float2*)(D + (size_t)r * ldd + gcol) = make_float2(v0, v1);
            if (r + 8 < NN) *(float2*)(D + (size_t)(r + 8) * ldd + gcol) = make_float2(v2, v3);
        }
    }
}

// ---------------- fp32 SGEMM (input projection, K=84) ------------------------
// ACT: 1=gelu, 2=gelu+tf32r
template <int ACT>
__global__ void k_gemm(const float* __restrict__ A, const float* __restrict__ B,
                       const float* __restrict__ bias, float* __restrict__ C,
                       int nrows, int K, int M, int ldc) {
    __shared__ float As[16][68];
    __shared__ float Bs[16][68];
    int bm = blockIdx.y * 64, bn = blockIdx.x * 64;
    int tid = threadIdx.x;
    int tx = tid & 15, ty = tid >> 4;
    int ar = tid >> 2, ak = (tid & 3) * 4;
    int br = tid >> 4, bc = (tid & 15) * 4;
    float acc[4][4];
#pragma unroll
    for (int i = 0; i < 4; i++)
#pragma unroll
        for (int j = 0; j < 4; j++) acc[i][j] = 0.f;
    int arow = bm + ar;
    for (int k0 = 0; k0 < K; k0 += 16) {
        float a0 = 0.f, a1 = 0.f, a2 = 0.f, a3 = 0.f;
        if (arow < nrows) {
            const float* ap = A + (size_t)arow * K + k0 + ak;
            if (k0 + ak + 4 <= K) {
                float4 v = *(const float4*)ap;
                a0 = v.x; a1 = v.y; a2 = v.z; a3 = v.w;
            } else {
                int rem = K - (k0 + ak);
                if (rem > 0) a0 = ap[0];
                if (rem > 1) a1 = ap[1];
                if (rem > 2) a2 = ap[2];
                if (rem > 3) a3 = ap[3];
            }
        }
        As[ak + 0][ar] = a0; As[ak + 1][ar] = a1;
        As[ak + 2][ar] = a2; As[ak + 3][ar] = a3;
        float4 bv = make_float4(0.f, 0.f, 0.f, 0.f);
        if (k0 + br < K) bv = *(const float4*)(B + (size_t)(k0 + br) * M + bn + bc);
        *(float4*)&Bs[br][bc] = bv;
        __syncthreads();
#pragma unroll
        for (int k = 0; k < 16; k++) {
            float4 av = *(const float4*)&As[k][ty * 4];
            float4 bw = *(const float4*)&Bs[k][tx * 4];
            float a[4] = {av.x, av.y, av.z, av.w};
            float bb[4] = {bw.x, bw.y, bw.z, bw.w};
#pragma unroll
            for (int i = 0; i < 4; i++)
#pragma unroll
                for (int j = 0; j < 4; j++) acc[i][j] += a[i] * bb[j];
        }
        __syncthreads();
    }
#pragma unroll
    for (int i = 0; i < 4; i++) {
        int row = bm + ty * 4 + i;
        if (row >= nrows) continue;
#pragma unroll
        for (int j = 0; j < 4; j++) {
            int col = bn + tx * 4 + j;
            if (col >= M) continue;
            float v = acc[i][j] + bias[col];
            v = gelu_f(v);
            if (ACT == 2) v = tf32r(v);
            C[(size_t)row * ldc + col] = v;
        }
    }
}

// ---------------- SpMM: float4, 64 threads/node, 4 nodes/block ---------------
// inputs are always 256-wide contiguous slabs; outputs may have ld 256 or 1024
struct SpArgs {
    const float* i0; const float* i1; const float* i2;
    float* o0; float* o1; float* o2;
    const float* bias;           // applied for y==0 only
    int ld0, ld1, ld2;
};
__global__ void __launch_bounds__(256) k_spmm(SpArgs a) {
    int y = blockIdx.y;
    const float* in = (y == 0) ? a.i0 : (y == 1) ? a.i1 : a.i2;
    float* out = (y == 0) ? a.o0 : (y == 1) ? a.o1 : a.o2;
    int ldo = (y == 0) ? a.ld0 : (y == 1) ? a.ld1 : a.ld2;
    int node = blockIdx.x * 4 + (threadIdx.x >> 6);
    int t = threadIdx.x & 63;
    if (node >= NN) return;
    const float4* in4 = (const float4*)in;
    int beg = g_rowptr[node], end = g_rowptr[node + 1];
    float di = g_dinv[node];
    float4 h = in4[(size_t)node * 64 + t];
    float w0 = di * di;
    float4 acc = make_float4(w0 * h.x, w0 * h.y, w0 * h.z, w0 * h.w);
    for (int e = beg; e < end; e++) {
        float w = __ldg(&g_ew[e]);
        float4 v = in4[(size_t)__ldg(&g_col[e]) * 64 + t];
        acc.x += w * v.x; acc.y += w * v.y; acc.z += w * v.z; acc.w += w * v.w;
    }
    if (y == 0 && a.bias) {
        const float4 b = *(const float4*)(a.bias + t * 4);
        acc.x += b.x; acc.y += b.y; acc.z += b.z; acc.w += b.w;
    }
    *(float4*)(out + (size_t)node * ldo + t * 4) = acc;
}

// ---------------- LayerNorm(1024) + GELU -> tf32-rounded g_af ----------------
__global__ void k_ln(const float* __restrict__ h, const float* __restrict__ g,
                     const float* __restrict__ bta, float* __restrict__ af) {
    int node = blockIdx.x;
    int tid = threadIdx.x;
    const float* row = h + (size_t)node * 1024;
    float v[4];
    float s = 0.f, ss = 0.f;
#pragma unroll
    for (int i = 0; i < 4; i++) {
        v[i] = row[tid + i * 256];
        s += v[i]; ss += v[i] * v[i];
    }
    __shared__ float shs[8], shss[8];
#pragma unroll
    for (int o = 16; o; o >>= 1) {
        s += __shfl_down_sync(0xffffffffu, s, o);
        ss += __shfl_down_sync(0xffffffffu, ss, o);
    }
    int w = tid >> 5, lane = tid & 31;
    if (lane == 0) { shs[w] = s; shss[w] = ss; }
    __syncthreads();
    if (w == 0) {
        s = (lane < 8) ? shs[lane] : 0.f;
        ss = (lane < 8) ? shss[lane] : 0.f;
#pragma unroll
        for (int o = 4; o; o >>= 1) {
            s += __shfl_down_sync(0xffffffffu, s, o);
            ss += __shfl_down_sync(0xffffffffu, ss, o);
        }
        if (lane == 0) { shs[0] = s; shss[0] = ss; }
    }
    __syncthreads();
    float mu = shs[0] * (1.0f / 1024.0f);
    float var = shss[0] * (1.0f / 1024.0f) - mu * mu;
    float inv = rsqrtf(var + 1e-5f);
#pragma unroll
    for (int i = 0; i < 4; i++) {
        int c = tid + i * 256;
        float t = (v[i] - mu) * inv * g[c] + bta[c];
        af[(size_t)node * 1024 + c] = tf32r(gelu_f(t));
    }
}

// ---------------- final dot --------------------------------------------------
__global__ void k_out(const float* __restrict__ h2, const float* __restrict__ w3,
                      const float* __restrict__ b3, float* __restrict__ out, int n) {
    int gw = (blockIdx.x * blockDim.x + threadIdx.x) >> 5;
    int lane = threadIdx.x & 31;
    if (gw >= n) return;
    const float* row = h2 + (size_t)gw * 128;
    float s = 0.f;
#pragma unroll
    for (int i = 0; i < 4; i++) s += row[lane + i * 32] * w3[lane + i * 32];
#pragma unroll
    for (int o = 16; o; o >>= 1) s += __shfl_down_sync(0xffffffffu, s, o);
    if (lane == 0) out[gw] = s + b3[0];
}

// ---------------- host orchestration -----------------------------------------
template <typename T>
static T* sym(const void* s) {
    void* p = nullptr;
    cudaGetSymbolAddress(&p, s);
    return (T*)p;
}

extern "C" void kernel_launch(void* const* d_in, const int* in_sizes, int n_in,
                              void* d_out, int out_size) {
    const float* x      = (const float*)d_in[0];
    const int*   ei     = (const int*)d_in[1];
    const float* w_in   = (const float*)d_in[2];
    const float* b_in   = (const float*)d_in[3];
    const float* mh_w0  = (const float*)d_in[4];
    const float* mh_b0  = (const float*)d_in[5];
    const float* mh_w12 = (const float*)d_in[6];
    const float* mh_b12 = (const float*)d_in[7];
    const float* ln_g   = (const float*)d_in[8];
    const float* ln_b   = (const float*)d_in[9];
    const float* w1     = (const float*)d_in[10];
    const float* b1     = (const float*)d_in[11];
    const float* w2     = (const float*)d_in[12];
    const float* b2     = (const float*)d_in[13];
    const float* w3     = (const float*)d_in[14];
    const float* b3     = (const float*)d_in[15];
    float* out = (float*)d_out;

    float* cat  = sym<float>(g_cat);
    float* tmp  = sym<float>(g_tmp);
    float* u2   = sym<float>(g_u2);
    float* mlp  = sym<float>(g_mlp);
    float* mlp2 = sym<float>(g_mlp2);
    float* af   = sym<float>(g_af);
    float* wt   = sym<float>(g_wt);

    static bool attr_done = false;
    if (!attr_done) {
        cudaFuncSetAttribute(k_mma, cudaFuncAttributeMaxDynamicSharedMemorySize, 98304);
        attr_done = true;
    }

    // graph preprocessing
    k_zero<<<(NN + 255) / 256, 256>>>();
    k_count<<<(EE + 255) / 256, 256>>>(ei);
    k_dinvk<<<(NN + 255) / 256, 256>>>();
    k_scan<<<1, 1024>>>();
    k_scatter<<<(EE + 255) / 256, 256>>>(ei);

    // weight conversion (transposed, tf32-rounded)
    const size_t OFF_L0 = 0, OFF_L1 = 262144, OFF_W1 = 2359296, OFF_W2 = 2621440;
    k_wconv<<<dim3(256, 4), 256>>>(mh_w0, wt + OFF_L0, 256, 256, 65536, 65536);
    k_wconv<<<dim3(1024, 8), 256>>>(mh_w12, wt + OFF_L1, 1024, 256, 262144, 262144);
    k_wconv<<<dim3(1024, 1), 256>>>(w1, wt + OFF_W1, 1024, 256, 262144, 262144);
    k_wconv<<<dim3(128, 1), 256>>>(w2, wt + OFF_W2, 256, 128, 32768, 32768);

    // input projection: gelu + tf32 round, straight into af [NN,256]
    k_gemm<2><<<dim3(4, (NN + 63) / 64), 256>>>(x, w_in, b_in, af, NN, 84, 256, 256);

    float* t1 = tmp;
    float* t2 = tmp + (size_t)NN * 256;
    float* t3 = tmp + (size_t)2 * NN * 256;
    float* ua = tmp + (size_t)3 * NN * 256;
    const int SPG = (NN + 3) / 4;

    auto LAYER = [&](int K, size_t woff, const float* bb,
                     const float* lg, const float* lb) {
        GOut o;
        o.p[0] = cat; o.p[1] = t1; o.p[2] = t2; o.p[3] = t3;
        o.b[0] = bb;  o.b[1] = nullptr; o.b[2] = nullptr; o.b[3] = nullptr;
        o.ld[0] = 1024; o.ld[1] = 256; o.ld[2] = 256; o.ld[3] = 256;
        o.act = 0;
        k_mma<<<dim3(8, 79), 128, 98304>>>(af, wt + woff, o, K);
        SpArgs h1{t1, t2, t3, cat + 256, ua, u2, bb + 256, 1024, 256, 256};
        k_spmm<<<dim3(SPG, 3), 256>>>(h1);
        SpArgs h2a{ua, u2, nullptr, cat + 512, t1, nullptr, bb + 512, 1024, 256, 0};
        k_spmm<<<dim3(SPG, 2), 256>>>(h2a);
        SpArgs h3{t1, nullptr, nullptr, cat + 768, nullptr, nullptr, bb + 768, 1024, 0, 0};
        k_spmm<<<dim3(SPG, 1), 256>>>(h3);
        k_ln<<<NN, 256>>>(cat, lg, lb, af);
    };

    LAYER(256,  OFF_L0,              mh_b0,         ln_g,        ln_b);
    LAYER(1024, OFF_L1,              mh_b12,        ln_g + 1024, ln_b + 1024);
    LAYER(1024, OFF_L1 + 4 * 262144, mh_b12 + 1024, ln_g + 2048, ln_b + 2048);

    // head MLP: w1 (gelu + tf32 round) -> w2 (gelu) -> dot
    GOut oh;
    oh.p[0] = mlp; oh.p[1] = nullptr; oh.p[2] = nullptr; oh.p[3] = nullptr;
    oh.b[0] = b1;  oh.b[1] = nullptr; oh.b[2] = nullptr; oh.b[3] = nullptr;
    oh.ld[0] = 256; oh.ld[1] = 0; oh.ld[2] = 0; oh.ld[3] = 0;
    oh.act = 2;
    k_mma<<<dim3(2, 79), 128, 98304>>>(af, wt + OFF_W1, oh, 1024);

    GOut o2;
    o2.p[0] = mlp2; o2.p[1] = nullptr; o2.p[2] = nullptr; o2.p[3] = nullptr;
    o2.b[0] = b2;   o2.b[1] = nullptr; o2.b[2] = nullptr; o2.b[3] = nullptr;
    o2.ld[0] = 128; o2.ld[1] = 0; o2.ld[2] = 0; o2.ld[3] = 0;
    o2.act = 1;
    k_mma<<<dim3(1, 79), 128, 98304>>>(mlp, wt + OFF_W2, o2, 256);

    k_out<<<(NN * 32 + 255) / 256, 256>>>(mlp2, w3, b3, out, NN);
}

// round 6
// speedup vs baseline: 3.9365x; 1.0712x over previous
#include <cuda_runtime.h>
#include <cuda_bf16.h>
#include <math.h>
#include <stdint.h>

#define NN 10000
#define EE 160000

// ---------------- scratch (device globals) ----------------------------------
__device__ float g_dinv[NN];
__device__ int   g_count[NN];
__device__ int   g_fill[NN];
__device__ int   g_rowptr[NN + 1];
__device__ int   g_col[EE];
__device__ float g_ew[EE];
__device__ float g_cat[(size_t)NN * 1024];
__device__ float g_tmp[(size_t)NN * 1024];   // slabs t1,t2,t3,ua (NN*256 each)
__device__ float g_u2[NN * 256];
__device__ float g_mlp[NN * 256];
__device__ float g_mlp2[NN * 128];
__device__ float g_af[(size_t)NN * 1024];    // tf32-rounded GEMM input
#define WTOT 2654208
__device__ float g_wt[WTOT];                 // tf32-rounded transposed weights

__device__ __forceinline__ float gelu_f(float x) {
    return 0.5f * x * (1.0f + erff(x * 0.70710678118654752f));
}
__device__ __forceinline__ float tf32r(float x) {
    float r;
    asm("cvt.rna.tf32.f32 %0, %1;" : "=f"(r) : "f"(x));
    return r;
}
__device__ __forceinline__ uint32_t smem_u32(const void* p) {
    uint32_t a;
    asm("{ .reg .u64 t; cvta.to.shared.u64 t, %1; cvt.u32.u64 %0, t; }" : "=r"(a) : "l"(p));
    return a;
}
__device__ __forceinline__ void ldsm4(uint32_t& r0, uint32_t& r1, uint32_t& r2,
                                      uint32_t& r3, uint32_t addr) {
    asm volatile("ldmatrix.sync.aligned.m8n8.x4.shared.b16 {%0,%1,%2,%3}, [%4];"
                 : "=r"(r0), "=r"(r1), "=r"(r2), "=r"(r3) : "r"(addr));
}
__device__ __forceinline__ void mma_tf32(float* c, const uint32_t* a, const uint32_t* b) {
    asm volatile(
        "mma.sync.aligned.m16n8k8.row.col.f32.tf32.tf32.f32 "
        "{%0,%1,%2,%3}, {%4,%5,%6,%7}, {%8,%9}, {%0,%1,%2,%3};"
        : "+f"(c[0]), "+f"(c[1]), "+f"(c[2]), "+f"(c[3])
        : "r"(a[0]), "r"(a[1]), "r"(a[2]), "r"(a[3]), "r"(b[0]), "r"(b[1]));
}

// ---------------- graph preprocessing ---------------------------------------
__global__ void k_zero() {
    int i = blockIdx.x * blockDim.x + threadIdx.x;
    if (i < NN) { g_count[i] = 0; g_fill[i] = 0; }
}
__global__ void k_count(const int* __restrict__ ei) {
    int e = blockIdx.x * blockDim.x + threadIdx.x;
    if (e < EE) atomicAdd(&g_count[ei[EE + e]], 1);
}
__global__ void k_dinvk() {
    int i = blockIdx.x * blockDim.x + threadIdx.x;
    if (i < NN) g_dinv[i] = rsqrtf((float)(g_count[i] + 1));
}
// 1024-thread shuffle-based exclusive scan of g_count -> g_rowptr
__global__ void k_scan() {
    int tid = threadIdx.x, lane = tid & 31, w = tid >> 5;
    const int chunk = 10;   // ceil(10000/1024)
    int b = tid * chunk, e = min(b + chunk, NN);
    int local = 0;
    for (int i = b; i < e; i++) local += g_count[i];
    int v = local;
#pragma unroll
    for (int o = 1; o < 32; o <<= 1) {
        int t = __shfl_up_sync(0xffffffffu, v, o);
        if (lane >= o) v += t;
    }
    __shared__ int ws[32];
    if (lane == 31) ws[w] = v;
    __syncthreads();
    if (w == 0) {
        int s = ws[lane];
#pragma unroll
        for (int o = 1; o < 32; o <<= 1) {
            int t = __shfl_up_sync(0xffffffffu, s, o);
            if (lane >= o) s += t;
        }
        ws[lane] = s;
    }
    __syncthreads();
    int run = v - local + (w ? ws[w - 1] : 0);
    for (int i = b; i < e; i++) { int c = g_count[i]; g_rowptr[i] = run; run += c; }
    if (tid == 1023) g_rowptr[NN] = run;
}
__global__ void k_scatter(const int* __restrict__ ei) {
    int e = blockIdx.x * blockDim.x + threadIdx.x;
    if (e >= EE) return;
    int s = ei[e], d = ei[EE + e];
    int pos = g_rowptr[d] + atomicAdd(&g_fill[d], 1);
    g_col[pos] = s;
    g_ew[pos] = g_dinv[s] * g_dinv[d];
}

// ---------------- weight conversion (transposed, tf32-rounded) ---------------
__global__ void k_wconv(const float* __restrict__ src, float* __restrict__ dst,
                        int K, int N, size_t srcStride, size_t dstStride) {
    int m = blockIdx.y;
    int e = blockIdx.x * 256 + threadIdx.x;
    if (e >= K * N) return;
    int k = e / N, n = e % N;
    dst[m * dstStride + (size_t)n * K + k] = tf32r(src[m * srcStride + e]);
}

// ---------------- tf32 mma GEMM ----------------------------------------------
// Per 128-col range: own A (a[r]), dest (p[r], ld, bias). block 128x128,
// 4 warps 64x64, BK=32, 3-stage cp.async.
struct GOut {
    const float* a[4];
    float* p[4];
    const float* b[4];
    int ld[4];
    int act;   // 0 none, 1 gelu, 2 gelu+tf32r
};

__global__ void __launch_bounds__(128, 2) k_mma(
    const float* __restrict__ B, GOut o, int K) {
    extern __shared__ char smc[];
    uint32_t sb = smem_u32(smc);
    int tid = threadIdx.x, lane = tid & 31, wid = tid >> 5;
    int WM = wid >> 1, WN = wid & 1;
    int bm = blockIdx.y * 128, bn = blockIdx.x * 128;
    int range = bn >> 8;
    const float* A = o.a[range];
    const int NIT = K >> 5;

    float acc[4][8][4];
#pragma unroll
    for (int i = 0; i < 4; i++)
#pragma unroll
        for (int j = 0; j < 8; j++)
#pragma unroll
            for (int r = 0; r < 4; r++) acc[i][j][r] = 0.f;

    auto LOAD = [&](int it) {
        int st = it % 3;
        uint32_t da = sb + st * 32768;
        uint32_t db = da + 16384;
        int k0 = it << 5;
#pragma unroll
        for (int i = 0; i < 8; i++) {
            int idx = i * 128 + tid;
            int row = idx >> 3, c = idx & 7;
            uint32_t so = row * 128 + ((c ^ (row & 7)) << 4);
            int ar = bm + row;
            const float* as = A + (size_t)min(ar, NN - 1) * K + k0 + c * 4;
            int sz = (ar < NN) ? 16 : 0;
            asm volatile("cp.async.cg.shared.global [%0], [%1], 16, %2;"
                         :: "r"(da + so), "l"(as), "r"(sz));
            const float* bs = B + (size_t)(bn + row) * K + k0 + c * 4;
            asm volatile("cp.async.cg.shared.global [%0], [%1], 16;"
                         :: "r"(db + so), "l"(bs));
        }
        asm volatile("cp.async.commit_group;");
    };

    LOAD(0);
    LOAD(1);
    for (int it = 0; it < NIT; it++) {
        asm volatile("cp.async.wait_group 1;");
        __syncthreads();
        if (it + 2 < NIT) LOAD(it + 2);
        int st = it % 3;
        uint32_t da = sb + st * 32768, db = da + 16384;
#pragma unroll
        for (int kk = 0; kk < 4; kk++) {
            uint32_t a[4][4], b[8][2];
#pragma unroll
            for (int mt = 0; mt < 4; mt++) {
                int row = WM * 64 + mt * 16 + (lane & 15);
                int ch = kk * 2 + (lane >> 4);
                uint32_t ad = da + row * 128 + ((ch ^ (row & 7)) << 4);
                ldsm4(a[mt][0], a[mt][1], a[mt][2], a[mt][3], ad);
            }
#pragma unroll
            for (int ng = 0; ng < 4; ng++) {
                int row = WN * 64 + ng * 16 + (lane & 7) + ((lane & 16) >> 1);
                int ch = kk * 2 + ((lane >> 3) & 1);
                uint32_t bd = db + row * 128 + ((ch ^ (row & 7)) << 4);
                ldsm4(b[2 * ng][0], b[2 * ng][1], b[2 * ng + 1][0], b[2 * ng + 1][1], bd);
            }
#pragma unroll
            for (int mt = 0; mt < 4; mt++)
#pragma unroll
                for (int nt = 0; nt < 8; nt++)
                    mma_tf32(acc[mt][nt], a[mt], b[nt]);
        }
    }

    float* D = o.p[range];
    const float* bias = o.b[range];
    int ldd = o.ld[range];
    int act = o.act;
#pragma unroll
    for (int mt = 0; mt < 4; mt++) {
        int r = bm + WM * 64 + mt * 16 + (lane >> 2);
#pragma unroll
        for (int nt = 0; nt < 8; nt++) {
            int gcol = (bn & 255) + WN * 64 + nt * 8 + ((lane & 3) << 1);
            float b0 = 0.f, b1 = 0.f;
            if (bias) { b0 = bias[gcol]; b1 = bias[gcol + 1]; }
            float v0 = acc[mt][nt][0] + b0, v1 = acc[mt][nt][1] + b1;
            float v2 = acc[mt][nt][2] + b0, v3 = acc[mt][nt][3] + b1;
            if (act) {
                v0 = gelu_f(v0); v1 = gelu_f(v1); v2 = gelu_f(v2); v3 = gelu_f(v3);
                if (act == 2) { v0 = tf32r(v0); v1 = tf32r(v1); v2 = tf32r(v2); v3 = tf32r(v3); }
            }
            if (r < NN) *(float2*)(D + (size_t)r * ldd + gcol) = make_float2(v0, v1);
            if (r + 8 < NN) *(float2*)(D + (size_t)(r + 8) * ldd + gcol) = make_float2(v2, v3);
        }
    }
}

// ---------------- fp32 SGEMM (input projection, K=84) ------------------------
template <int ACT>
__global__ void k_gemm(const float* __restrict__ A, const float* __restrict__ B,
                       const float* __restrict__ bias, float* __restrict__ C,
                       int nrows, int K, int M, int ldc) {
    __shared__ float As[16][68];
    __shared__ float Bs[16][68];
    int bm = blockIdx.y * 64, bn = blockIdx.x * 64;
    int tid = threadIdx.x;
    int tx = tid & 15, ty = tid >> 4;
    int ar = tid >> 2, ak = (tid & 3) * 4;
    int br = tid >> 4, bc = (tid & 15) * 4;
    float acc[4][4];
#pragma unroll
    for (int i = 0; i < 4; i++)
#pragma unroll
        for (int j = 0; j < 4; j++) acc[i][j] = 0.f;
    int arow = bm + ar;
    for (int k0 = 0; k0 < K; k0 += 16) {
        float a0 = 0.f, a1 = 0.f, a2 = 0.f, a3 = 0.f;
        if (arow < nrows) {
            const float* ap = A + (size_t)arow * K + k0 + ak;
            if (k0 + ak + 4 <= K) {
                float4 v = *(const float4*)ap;
                a0 = v.x; a1 = v.y; a2 = v.z; a3 = v.w;
            } else {
                int rem = K - (k0 + ak);
                if (rem > 0) a0 = ap[0];
                if (rem > 1) a1 = ap[1];
                if (rem > 2) a2 = ap[2];
                if (rem > 3) a3 = ap[3];
            }
        }
        As[ak + 0][ar] = a0; As[ak + 1][ar] = a1;
        As[ak + 2][ar] = a2; As[ak + 3][ar] = a3;
        float4 bv = make_float4(0.f, 0.f, 0.f, 0.f);
        if (k0 + br < K) bv = *(const float4*)(B + (size_t)(k0 + br) * M + bn + bc);
        *(float4*)&Bs[br][bc] = bv;
        __syncthreads();
#pragma unroll
        for (int k = 0; k < 16; k++) {
            float4 av = *(const float4*)&As[k][ty * 4];
            float4 bw = *(const float4*)&Bs[k][tx * 4];
            float a[4] = {av.x, av.y, av.z, av.w};
            float bb[4] = {bw.x, bw.y, bw.z, bw.w};
#pragma unroll
            for (int i = 0; i < 4; i++)
#pragma unroll
                for (int j = 0; j < 4; j++) acc[i][j] += a[i] * bb[j];
        }
        __syncthreads();
    }
#pragma unroll
    for (int i = 0; i < 4; i++) {
        int row = bm + ty * 4 + i;
        if (row >= nrows) continue;
#pragma unroll
        for (int j = 0; j < 4; j++) {
            int col = bn + tx * 4 + j;
            if (col >= M) continue;
            float v = acc[i][j] + bias[col];
            v = gelu_f(v);
            if (ACT == 2) v = tf32r(v);
            C[(size_t)row * ldc + col] = v;
        }
    }
}

// ---------------- SpMM: float4, 64 threads/node, 4 nodes/block ---------------
struct SpArgs {
    const float* i0; const float* i1; const float* i2;
    float* o0; float* o1; float* o2;
    const float* bias;           // applied for y==0 only
    int ld0, ld1, ld2;
    int rnd;                     // tf32-round outputs
};
__global__ void __launch_bounds__(256) k_spmm(SpArgs a) {
    int y = blockIdx.y;
    const float* in = (y == 0) ? a.i0 : (y == 1) ? a.i1 : a.i2;
    float* out = (y == 0) ? a.o0 : (y == 1) ? a.o1 : a.o2;
    int ldo = (y == 0) ? a.ld0 : (y == 1) ? a.ld1 : a.ld2;
    int node = blockIdx.x * 4 + (threadIdx.x >> 6);
    int t = threadIdx.x & 63;
    if (node >= NN) return;
    const float4* in4 = (const float4*)in;
    int beg = g_rowptr[node], end = g_rowptr[node + 1];
    float di = g_dinv[node];
    float4 h = in4[(size_t)node * 64 + t];
    float w0 = di * di;
    float4 acc = make_float4(w0 * h.x, w0 * h.y, w0 * h.z, w0 * h.w);
    for (int e = beg; e < end; e++) {
        float w = __ldg(&g_ew[e]);
        float4 v = in4[(size_t)__ldg(&g_col[e]) * 64 + t];
        acc.x += w * v.x; acc.y += w * v.y; acc.z += w * v.z; acc.w += w * v.w;
    }
    if (y == 0 && a.bias) {
        const float4 b = *(const float4*)(a.bias + t * 4);
        acc.x += b.x; acc.y += b.y; acc.z += b.z; acc.w += b.w;
    }
    if (a.rnd) {
        acc.x = tf32r(acc.x); acc.y = tf32r(acc.y);
        acc.z = tf32r(acc.z); acc.w = tf32r(acc.w);
    }
    *(float4*)(out + (size_t)node * ldo + t * 4) = acc;
}

// ---------------- LayerNorm(1024) + GELU -> tf32-rounded g_af ----------------
__global__ void k_ln(const float* __restrict__ h, const float* __restrict__ g,
                     const float* __restrict__ bta, float* __restrict__ af) {
    int node = blockIdx.x;
    int tid = threadIdx.x;
    const float* row = h + (size_t)node * 1024;
    float v[4];
    float s = 0.f, ss = 0.f;
#pragma unroll
    for (int i = 0; i < 4; i++) {
        v[i] = row[tid + i * 256];
        s += v[i]; ss += v[i] * v[i];
    }
    __shared__ float shs[8], shss[8];
#pragma unroll
    for (int o = 16; o; o >>= 1) {
        s += __shfl_down_sync(0xffffffffu, s, o);
        ss += __shfl_down_sync(0xffffffffu, ss, o);
    }
    int w = tid >> 5, lane = tid & 31;
    if (lane == 0) { shs[w] = s; shss[w] = ss; }
    __syncthreads();
    if (w == 0) {
        s = (lane < 8) ? shs[lane] : 0.f;
        ss = (lane < 8) ? shss[lane] : 0.f;
#pragma unroll
        for (int o = 4; o; o >>= 1) {
            s += __shfl_down_sync(0xffffffffu, s, o);
            ss += __shfl_down_sync(0xffffffffu, ss, o);
        }
        if (lane == 0) { shs[0] = s; shss[0] = ss; }
    }
    __syncthreads();
    float mu = shs[0] * (1.0f / 1024.0f);
    float var = shss[0] * (1.0f / 1024.0f) - mu * mu;
    float inv = rsqrtf(var + 1e-5f);
#pragma unroll
    for (int i = 0; i < 4; i++) {
        int c = tid + i * 256;
        float t = (v[i] - mu) * inv * g[c] + bta[c];
        af[(size_t)node * 1024 + c] = tf32r(gelu_f(t));
    }
}

// ---------------- final dot --------------------------------------------------
__global__ void k_out(const float* __restrict__ h2, const float* __restrict__ w3,
                      const float* __restrict__ b3, float* __restrict__ out, int n) {
    int gw = (blockIdx.x * blockDim.x + threadIdx.x) >> 5;
    int lane = threadIdx.x & 31;
    if (gw >= n) return;
    const float* row = h2 + (size_t)gw * 128;
    float s = 0.f;
#pragma unroll
    for (int i = 0; i < 4; i++) s += row[lane + i * 32] * w3[lane + i * 32];
#pragma unroll
    for (int o = 16; o; o >>= 1) s += __shfl_down_sync(0xffffffffu, s, o);
    if (lane == 0) out[gw] = s + b3[0];
}

// ---------------- host orchestration -----------------------------------------
template <typename T>
static T* sym(const void* s) {
    void* p = nullptr;
    cudaGetSymbolAddress(&p, s);
    return (T*)p;
}

extern "C" void kernel_launch(void* const* d_in, const int* in_sizes, int n_in,
                              void* d_out, int out_size) {
    const float* x      = (const float*)d_in[0];
    const int*   ei     = (const int*)d_in[1];
    const float* w_in   = (const float*)d_in[2];
    const float* b_in   = (const float*)d_in[3];
    const float* mh_w0  = (const float*)d_in[4];
    const float* mh_b0  = (const float*)d_in[5];
    const float* mh_w12 = (const float*)d_in[6];
    const float* mh_b12 = (const float*)d_in[7];
    const float* ln_g   = (const float*)d_in[8];
    const float* ln_b   = (const float*)d_in[9];
    const float* w1     = (const float*)d_in[10];
    const float* b1     = (const float*)d_in[11];
    const float* w2     = (const float*)d_in[12];
    const float* b2     = (const float*)d_in[13];
    const float* w3     = (const float*)d_in[14];
    const float* b3     = (const float*)d_in[15];
    float* out = (float*)d_out;

    float* cat  = sym<float>(g_cat);
    float* tmp  = sym<float>(g_tmp);
    float* u2   = sym<float>(g_u2);
    float* mlp  = sym<float>(g_mlp);
    float* mlp2 = sym<float>(g_mlp2);
    float* af   = sym<float>(g_af);
    float* wt   = sym<float>(g_wt);

    static cudaStream_t s1 = nullptr, s2 = nullptr;
    static cudaEvent_t ev0 = nullptr, ev1 = nullptr, ev2 = nullptr, ev3 = nullptr;
    static bool init_done = false;
    if (!init_done) {
        cudaFuncSetAttribute(k_mma, cudaFuncAttributeMaxDynamicSharedMemorySize, 98304);
        cudaStreamCreateWithFlags(&s1, cudaStreamNonBlocking);
        cudaStreamCreateWithFlags(&s2, cudaStreamNonBlocking);
        cudaEventCreateWithFlags(&ev0, cudaEventDisableTiming);
        cudaEventCreateWithFlags(&ev1, cudaEventDisableTiming);
        cudaEventCreateWithFlags(&ev2, cudaEventDisableTiming);
        cudaEventCreateWithFlags(&ev3, cudaEventDisableTiming);
        init_done = true;
    }

    const size_t OFF_L0 = 0, OFF_L1 = 262144, OFF_W1 = 2359296, OFF_W2 = 2621440;

    // fork side streams from capture stream (legacy default)
    cudaEventRecord(ev0, 0);
    cudaStreamWaitEvent(s1, ev0, 0);
    cudaStreamWaitEvent(s2, ev0, 0);

    // s1: graph preprocessing (CSR build) — needed only by SpMM
    k_zero<<<(NN + 255) / 256, 256, 0, s1>>>();
    k_count<<<(EE + 255) / 256, 256, 0, s1>>>(ei);
    k_dinvk<<<(NN + 255) / 256, 256, 0, s1>>>();
    k_scan<<<1, 1024, 0, s1>>>();
    k_scatter<<<(EE + 255) / 256, 256, 0, s1>>>(ei);
    cudaEventRecord(ev1, s1);

    // s2: big weight conversions — needed from layer 1 onward
    k_wconv<<<dim3(1024, 8), 256, 0, s2>>>(mh_w12, wt + OFF_L1, 1024, 256, 262144, 262144);
    k_wconv<<<dim3(1024, 1), 256, 0, s2>>>(w1, wt + OFF_W1, 1024, 256, 262144, 262144);
    k_wconv<<<dim3(128, 1), 256, 0, s2>>>(w2, wt + OFF_W2, 256, 128, 32768, 32768);
    cudaEventRecord(ev2, s2);

    // main: layer-0 weights + input projection (gelu+tf32r into af)
    k_wconv<<<dim3(256, 4), 256>>>(mh_w0, wt + OFF_L0, 256, 256, 65536, 65536);
    k_gemm<2><<<dim3(4, (NN + 63) / 64), 256>>>(x, w_in, b_in, af, NN, 84, 256, 256);

    float* t1 = tmp;
    float* t2 = tmp + (size_t)NN * 256;
    float* t3 = tmp + (size_t)2 * NN * 256;
    float* ua = tmp + (size_t)3 * NN * 256;
    const int SPG = (NN + 3) / 4;

    // ---- layer 0: propagate-first (h is 256-wide) ----
    cudaStreamWaitEvent(0, ev1, 0);   // CSR ready
    {
        SpArgs p1{af, nullptr, nullptr, t1, nullptr, nullptr, nullptr, 256, 0, 0, 1};
        k_spmm<<<dim3(SPG, 1), 256>>>(p1);
        SpArgs p2{t1, nullptr, nullptr, t2, nullptr, nullptr, nullptr, 256, 0, 0, 1};
        k_spmm<<<dim3(SPG, 1), 256>>>(p2);
        SpArgs p3{t2, nullptr, nullptr, t3, nullptr, nullptr, nullptr, 256, 0, 0, 1};
        k_spmm<<<dim3(SPG, 1), 256>>>(p3);
        GOut o;
        o.a[0] = af; o.a[1] = t1; o.a[2] = t2; o.a[3] = t3;
        o.p[0] = cat; o.p[1] = cat + 256; o.p[2] = cat + 512; o.p[3] = cat + 768;
        o.b[0] = mh_b0; o.b[1] = mh_b0 + 256; o.b[2] = mh_b0 + 512; o.b[3] = mh_b0 + 768;
        o.ld[0] = o.ld[1] = o.ld[2] = o.ld[3] = 1024;
        o.act = 0;
        k_mma<<<dim3(8, 79), 128, 98304>>>(wt + OFF_L0, o, 256);
        k_ln<<<NN, 256>>>(cat, ln_g, ln_b, af);
    }

    cudaStreamWaitEvent(0, ev2, 0);   // big weights ready

    // ---- layers 1,2: GEMM-first (K=1024, propagate in 256-wide output space) --
    auto LAYER = [&](size_t woff, const float* bb, const float* lg, const float* lb) {
        GOut o;
        o.a[0] = o.a[1] = o.a[2] = o.a[3] = af;
        o.p[0] = cat; o.p[1] = t1; o.p[2] = t2; o.p[3] = t3;
        o.b[0] = bb;  o.b[1] = nullptr; o.b[2] = nullptr; o.b[3] = nullptr;
        o.ld[0] = 1024; o.ld[1] = 256; o.ld[2] = 256; o.ld[3] = 256;
        o.act = 0;
        k_mma<<<dim3(8, 79), 128, 98304>>>(wt + woff, o, 1024);
        SpArgs h1{t1, t2, t3, cat + 256, ua, u2, bb + 256, 1024, 256, 256, 0};
        k_spmm<<<dim3(SPG, 3), 256>>>(h1);
        SpArgs h2a{ua, u2, nullptr, cat + 512, t1, nullptr, bb + 512, 1024, 256, 0, 0};
        k_spmm<<<dim3(SPG, 2), 256>>>(h2a);
        SpArgs h3{t1, nullptr, nullptr, cat + 768, nullptr, nullptr, bb + 768, 1024, 0, 0, 0};
        k_spmm<<<dim3(SPG, 1), 256>>>(h3);
        k_ln<<<NN, 256>>>(cat, lg, lb, af);
    };

    LAYER(OFF_L1,              mh_b12,        ln_g + 1024, ln_b + 1024);
    LAYER(OFF_L1 + 4 * 262144, mh_b12 + 1024, ln_g + 2048, ln_b + 2048);

    // ---- head MLP ----
    GOut oh;
    oh.a[0] = af; oh.a[1] = oh.a[2] = oh.a[3] = nullptr;
    oh.p[0] = mlp; oh.p[1] = oh.p[2] = oh.p[3] = nullptr;
    oh.b[0] = b1;  oh.b[1] = oh.b[2] = oh.b[3] = nullptr;
    oh.ld[0] = 256; oh.ld[1] = oh.ld[2] = oh.ld[3] = 0;
    oh.act = 2;
    k_mma<<<dim3(2, 79), 128, 98304>>>(wt + OFF_W1, oh, 1024);

    GOut o2;
    o2.a[0] = mlp; o2.a[1] = o2.a[2] = o2.a[3] = nullptr;
    o2.p[0] = mlp2; o2.p[1] = o2.p[2] = o2.p[3] = nullptr;
    o2.b[0] = b2;   o2.b[1] = o2.b[2] = o2.b[3] = nullptr;
    o2.ld[0] = 128; o2.ld[1] = o2.ld[2] = o2.ld[3] = 0;
    o2.act = 1;
    k_mma<<<dim3(1, 79), 128, 98304>>>(wt + OFF_W2, o2, 256);

    k_out<<<(NN * 32 + 255) / 256, 256>>>(mlp2, w3, b3, out, NN);
}

// round 7
// speedup vs baseline: 4.0595x; 1.0312x over previous
#include <cuda_runtime.h>
#include <cuda_bf16.h>
#include <math.h>
#include <stdint.h>

#define NN 10000
#define EE 160000

// ---------------- scratch (device globals) ----------------------------------
__device__ float g_dinv[NN];
__device__ int   g_count[NN];
__device__ int   g_fill[NN];
__device__ int   g_rowptr[NN + 1];
__device__ int   g_col[EE];
__device__ float g_ew[EE];
__device__ float g_cat[(size_t)NN * 1024];
__device__ float g_tmp[(size_t)NN * 1024];   // slabs t1,t2,t3,ua (NN*256 each)
__device__ float g_u2[NN * 256];
__device__ float g_mlp[NN * 256];
__device__ float g_mlp2[NN * 128];
__device__ float g_af[(size_t)NN * 1024];    // tf32-rounded GEMM input
#define WTOT 2654208
__device__ float g_wt[WTOT];                 // tf32-rounded transposed weights

__device__ __forceinline__ float gelu_f(float x) {
    return 0.5f * x * (1.0f + erff(x * 0.70710678118654752f));
}
__device__ __forceinline__ float tf32r(float x) {
    float r;
    asm("cvt.rna.tf32.f32 %0, %1;" : "=f"(r) : "f"(x));
    return r;
}
__device__ __forceinline__ uint32_t smem_u32(const void* p) {
    uint32_t a;
    asm("{ .reg .u64 t; cvta.to.shared.u64 t, %1; cvt.u32.u64 %0, t; }" : "=r"(a) : "l"(p));
    return a;
}
__device__ __forceinline__ void ldsm4(uint32_t& r0, uint32_t& r1, uint32_t& r2,
                                      uint32_t& r3, uint32_t addr) {
    asm volatile("ldmatrix.sync.aligned.m8n8.x4.shared.b16 {%0,%1,%2,%3}, [%4];"
                 : "=r"(r0), "=r"(r1), "=r"(r2), "=r"(r3) : "r"(addr));
}
__device__ __forceinline__ void mma_tf32(float* c, const uint32_t* a, const uint32_t* b) {
    asm volatile(
        "mma.sync.aligned.m16n8k8.row.col.f32.tf32.tf32.f32 "
        "{%0,%1,%2,%3}, {%4,%5,%6,%7}, {%8,%9}, {%0,%1,%2,%3};"
        : "+f"(c[0]), "+f"(c[1]), "+f"(c[2]), "+f"(c[3])
        : "r"(a[0]), "r"(a[1]), "r"(a[2]), "r"(a[3]), "r"(b[0]), "r"(b[1]));
}

// ---------------- graph preprocessing ---------------------------------------
__global__ void k_zero() {
    int i = blockIdx.x * blockDim.x + threadIdx.x;
    if (i < NN) { g_count[i] = 0; g_fill[i] = 0; }
}
__global__ void k_count(const int* __restrict__ ei) {
    int e = blockIdx.x * blockDim.x + threadIdx.x;
    if (e < EE) atomicAdd(&g_count[ei[EE + e]], 1);
}
__global__ void k_dinvk() {
    int i = blockIdx.x * blockDim.x + threadIdx.x;
    if (i < NN) g_dinv[i] = rsqrtf((float)(g_count[i] + 1));
}
__global__ void k_scan() {
    int tid = threadIdx.x, lane = tid & 31, w = tid >> 5;
    const int chunk = 10;
    int b = tid * chunk, e = min(b + chunk, NN);
    int local = 0;
    for (int i = b; i < e; i++) local += g_count[i];
    int v = local;
#pragma unroll
    for (int o = 1; o < 32; o <<= 1) {
        int t = __shfl_up_sync(0xffffffffu, v, o);
        if (lane >= o) v += t;
    }
    __shared__ int ws[32];
    if (lane == 31) ws[w] = v;
    __syncthreads();
    if (w == 0) {
        int s = ws[lane];
#pragma unroll
        for (int o = 1; o < 32; o <<= 1) {
            int t = __shfl_up_sync(0xffffffffu, s, o);
            if (lane >= o) s += t;
        }
        ws[lane] = s;
    }
    __syncthreads();
    int run = v - local + (w ? ws[w - 1] : 0);
    for (int i = b; i < e; i++) { int c = g_count[i]; g_rowptr[i] = run; run += c; }
    if (tid == 1023) g_rowptr[NN] = run;
}
__global__ void k_scatter(const int* __restrict__ ei) {
    int e = blockIdx.x * blockDim.x + threadIdx.x;
    if (e >= EE) return;
    int s = ei[e], d = ei[EE + e];
    int pos = g_rowptr[d] + atomicAdd(&g_fill[d], 1);
    g_col[pos] = s;
    g_ew[pos] = g_dinv[s] * g_dinv[d];
}

// ---------------- weight conversion (transposed, tf32-rounded) ---------------
__global__ void k_wconv(const float* __restrict__ src, float* __restrict__ dst,
                        int K, int N, size_t srcStride, size_t dstStride) {
    int m = blockIdx.y;
    int e = blockIdx.x * 256 + threadIdx.x;
    if (e >= K * N) return;
    int k = e / N, n = e % N;
    dst[m * dstStride + (size_t)n * K + k] = tf32r(src[m * srcStride + e]);
}

// ---------------- tf32 mma GEMM ----------------------------------------------
struct GOut {
    const float* a[4];
    float* p[4];
    const float* b[4];
    int ld[4];
    int act;   // 0 none, 1 gelu, 2 gelu+tf32r
};

__global__ void __launch_bounds__(128, 2) k_mma(
    const float* __restrict__ B, GOut o, int K, int bnoff) {
    extern __shared__ char smc[];
    uint32_t sb = smem_u32(smc);
    int tid = threadIdx.x, lane = tid & 31, wid = tid >> 5;
    int WM = wid >> 1, WN = wid & 1;
    int bm = blockIdx.y * 128, bn = (blockIdx.x + bnoff) * 128;
    int range = bn >> 8;
    const float* A = o.a[range];
    const int NIT = K >> 5;

    float acc[4][8][4];
#pragma unroll
    for (int i = 0; i < 4; i++)
#pragma unroll
        for (int j = 0; j < 8; j++)
#pragma unroll
            for (int r = 0; r < 4; r++) acc[i][j][r] = 0.f;

    auto LOAD = [&](int it) {
        int st = it % 3;
        uint32_t da = sb + st * 32768;
        uint32_t db = da + 16384;
        int k0 = it << 5;
#pragma unroll
        for (int i = 0; i < 8; i++) {
            int idx = i * 128 + tid;
            int row = idx >> 3, c = idx & 7;
            uint32_t so = row * 128 + ((c ^ (row & 7)) << 4);
            int ar = bm + row;
            const float* as = A + (size_t)min(ar, NN - 1) * K + k0 + c * 4;
            int sz = (ar < NN) ? 16 : 0;
            asm volatile("cp.async.cg.shared.global [%0], [%1], 16, %2;"
                         :: "r"(da + so), "l"(as), "r"(sz));
            const float* bs = B + (size_t)(bn + row) * K + k0 + c * 4;
            asm volatile("cp.async.cg.shared.global [%0], [%1], 16;"
                         :: "r"(db + so), "l"(bs));
        }
        asm volatile("cp.async.commit_group;");
    };

    LOAD(0);
    LOAD(1);
    for (int it = 0; it < NIT; it++) {
        asm volatile("cp.async.wait_group 1;");
        __syncthreads();
        if (it + 2 < NIT) LOAD(it + 2);
        int st = it % 3;
        uint32_t da = sb + st * 32768, db = da + 16384;
#pragma unroll
        for (int kk = 0; kk < 4; kk++) {
            uint32_t a[4][4], b[8][2];
#pragma unroll
            for (int mt = 0; mt < 4; mt++) {
                int row = WM * 64 + mt * 16 + (lane & 15);
                int ch = kk * 2 + (lane >> 4);
                uint32_t ad = da + row * 128 + ((ch ^ (row & 7)) << 4);
                ldsm4(a[mt][0], a[mt][1], a[mt][2], a[mt][3], ad);
            }
#pragma unroll
            for (int ng = 0; ng < 4; ng++) {
                int row = WN * 64 + ng * 16 + (lane & 7) + ((lane & 16) >> 1);
                int ch = kk * 2 + ((lane >> 3) & 1);
                uint32_t bd = db + row * 128 + ((ch ^ (row & 7)) << 4);
                ldsm4(b[2 * ng][0], b[2 * ng][1], b[2 * ng + 1][0], b[2 * ng + 1][1], bd);
            }
#pragma unroll
            for (int mt = 0; mt < 4; mt++)
#pragma unroll
                for (int nt = 0; nt < 8; nt++)
                    mma_tf32(acc[mt][nt], a[mt], b[nt]);
        }
    }

    float* D = o.p[range];
    const float* bias = o.b[range];
    int ldd = o.ld[range];
    int act = o.act;
#pragma unroll
    for (int mt = 0; mt < 4; mt++) {
        int r = bm + WM * 64 + mt * 16 + (lane >> 2);
#pragma unroll
        for (int nt = 0; nt < 8; nt++) {
            int gcol = (bn & 255) + WN * 64 + nt * 8 + ((lane & 3) << 1);
            float b0 = 0.f, b1 = 0.f;
            if (bias) { b0 = bias[gcol]; b1 = bias[gcol + 1]; }
            float v0 = acc[mt][nt][0] + b0, v1 = acc[mt][nt][1] + b1;
            float v2 = acc[mt][nt][2] + b0, v3 = acc[mt][nt][3] + b1;
            if (act) {
                v0 = gelu_f(v0); v1 = gelu_f(v1); v2 = gelu_f(v2); v3 = gelu_f(v3);
                if (act == 2) { v0 = tf32r(v0); v1 = tf32r(v1); v2 = tf32r(v2); v3 = tf32r(v3); }
            }
            if (r < NN) *(float2*)(D + (size_t)r * ldd + gcol) = make_float2(v0, v1);
            if (r + 8 < NN) *(float2*)(D + (size_t)(r + 8) * ldd + gcol) = make_float2(v2, v3);
        }
    }
}

// ---------------- fp32 SGEMM (input projection, K=84) ------------------------
template <int ACT>
__global__ void k_gemm(const float* __restrict__ A, const float* __restrict__ B,
                       const float* __restrict__ bias, float* __restrict__ C,
                       int nrows, int K, int M, int ldc) {
    __shared__ float As[16][68];
    __shared__ float Bs[16][68];
    int bm = blockIdx.y * 64, bn = blockIdx.x * 64;
    int tid = threadIdx.x;
    int tx = tid & 15, ty = tid >> 4;
    int ar = tid >> 2, ak = (tid & 3) * 4;
    int br = tid >> 4, bc = (tid & 15) * 4;
    float acc[4][4];
#pragma unroll
    for (int i = 0; i < 4; i++)
#pragma unroll
        for (int j = 0; j < 4; j++) acc[i][j] = 0.f;
    int arow = bm + ar;
    for (int k0 = 0; k0 < K; k0 += 16) {
        float a0 = 0.f, a1 = 0.f, a2 = 0.f, a3 = 0.f;
        if (arow < nrows) {
            const float* ap = A + (size_t)arow * K + k0 + ak;
            if (k0 + ak + 4 <= K) {
                float4 v = *(const float4*)ap;
                a0 = v.x; a1 = v.y; a2 = v.z; a3 = v.w;
            } else {
                int rem = K - (k0 + ak);
                if (rem > 0) a0 = ap[0];
                if (rem > 1) a1 = ap[1];
                if (rem > 2) a2 = ap[2];
                if (rem > 3) a3 = ap[3];
            }
        }
        As[ak + 0][ar] = a0; As[ak + 1][ar] = a1;
        As[ak + 2][ar] = a2; As[ak + 3][ar] = a3;
        float4 bv = make_float4(0.f, 0.f, 0.f, 0.f);
        if (k0 + br < K) bv = *(const float4*)(B + (size_t)(k0 + br) * M + bn + bc);
        *(float4*)&Bs[br][bc] = bv;
        __syncthreads();
#pragma unroll
        for (int k = 0; k < 16; k++) {
            float4 av = *(const float4*)&As[k][ty * 4];
            float4 bw = *(const float4*)&Bs[k][tx * 4];
            float a[4] = {av.x, av.y, av.z, av.w};
            float bb[4] = {bw.x, bw.y, bw.z, bw.w};
#pragma unroll
            for (int i = 0; i < 4; i++)
#pragma unroll
                for (int j = 0; j < 4; j++) acc[i][j] += a[i] * bb[j];
        }
        __syncthreads();
    }
#pragma unroll
    for (int i = 0; i < 4; i++) {
        int row = bm + ty * 4 + i;
        if (row >= nrows) continue;
#pragma unroll
        for (int j = 0; j < 4; j++) {
            int col = bn + tx * 4 + j;
            if (col >= M) continue;
            float v = acc[i][j] + bias[col];
            v = gelu_f(v);
            if (ACT == 2) v = tf32r(v);
            C[(size_t)row * ldc + col] = v;
        }
    }
}

// ---------------- SpMM: float4, 64 threads/node, 4 nodes/block ---------------
struct SpArgs {
    const float* i0; const float* i1; const float* i2;
    float* o0; float* o1; float* o2;
    const float* bias;
    int ld0, ld1, ld2;
    int rnd;
};
__global__ void __launch_bounds__(256) k_spmm(SpArgs a) {
    int y = blockIdx.y;
    const float* in = (y == 0) ? a.i0 : (y == 1) ? a.i1 : a.i2;
    float* out = (y == 0) ? a.o0 : (y == 1) ? a.o1 : a.o2;
    int ldo = (y == 0) ? a.ld0 : (y == 1) ? a.ld1 : a.ld2;
    int node = blockIdx.x * 4 + (threadIdx.x >> 6);
    int t = threadIdx.x & 63;
    if (node >= NN) return;
    const float4* in4 = (const float4*)in;
    int beg = g_rowptr[node], end = g_rowptr[node + 1];
    float di = g_dinv[node];
    float4 h = in4[(size_t)node * 64 + t];
    float w0 = di * di;
    float4 acc = make_float4(w0 * h.x, w0 * h.y, w0 * h.z, w0 * h.w);
    for (int e = beg; e < end; e++) {
        float w = __ldg(&g_ew[e]);
        float4 v = in4[(size_t)__ldg(&g_col[e]) * 64 + t];
        acc.x += w * v.x; acc.y += w * v.y; acc.z += w * v.z; acc.w += w * v.w;
    }
    if (y == 0 && a.bias) {
        const float4 b = *(const float4*)(a.bias + t * 4);
        acc.x += b.x; acc.y += b.y; acc.z += b.z; acc.w += b.w;
    }
    if (a.rnd) {
        acc.x = tf32r(acc.x); acc.y = tf32r(acc.y);
        acc.z = tf32r(acc.z); acc.w = tf32r(acc.w);
    }
    *(float4*)(out + (size_t)node * ldo + t * 4) = acc;
}

// ---------------- fused: hop3 (slab 768) + LayerNorm + GELU -> af -------------
// 4 nodes/block, 64 threads/node. slab3 computed in registers (never hits gmem).
__global__ void __launch_bounds__(256) k_spmm_ln(
    const float* __restrict__ in, const float* __restrict__ cat,
    const float* __restrict__ bias, const float* __restrict__ lg,
    const float* __restrict__ lb, float* __restrict__ af) {
    int tid = threadIdx.x;
    int t = tid & 63;
    int node = blockIdx.x * 4 + (tid >> 6);   // NN % 4 == 0
    const float4* in4 = (const float4*)in;
    int beg = g_rowptr[node], end = g_rowptr[node + 1];
    float di = g_dinv[node];
    float4 h = in4[(size_t)node * 64 + t];
    float w0 = di * di;
    float4 a3 = make_float4(w0 * h.x, w0 * h.y, w0 * h.z, w0 * h.w);
    for (int e = beg; e < end; e++) {
        float w = __ldg(&g_ew[e]);
        float4 v = in4[(size_t)__ldg(&g_col[e]) * 64 + t];
        a3.x += w * v.x; a3.y += w * v.y; a3.z += w * v.z; a3.w += w * v.w;
    }
    {
        const float4 b4 = *(const float4*)(bias + t * 4);
        a3.x += b4.x; a3.y += b4.y; a3.z += b4.z; a3.w += b4.w;
    }
    const float* crow = cat + (size_t)node * 1024;
    float4 v0 = *(const float4*)(crow + t * 4);
    float4 v1 = *(const float4*)(crow + 256 + t * 4);
    float4 v2 = *(const float4*)(crow + 512 + t * 4);
    float s = v0.x + v0.y + v0.z + v0.w + v1.x + v1.y + v1.z + v1.w +
              v2.x + v2.y + v2.z + v2.w + a3.x + a3.y + a3.z + a3.w;
    float ss = v0.x*v0.x + v0.y*v0.y + v0.z*v0.z + v0.w*v0.w +
               v1.x*v1.x + v1.y*v1.y + v1.z*v1.z + v1.w*v1.w +
               v2.x*v2.x + v2.y*v2.y + v2.z*v2.z + v2.w*v2.w +
               a3.x*a3.x + a3.y*a3.y + a3.z*a3.z + a3.w*a3.w;
    int w_ = tid >> 5, lane = tid & 31;
#pragma unroll
    for (int o = 16; o; o >>= 1) {
        s += __shfl_down_sync(0xffffffffu, s, o);
        ss += __shfl_down_sync(0xffffffffu, ss, o);
    }
    __shared__ float gs[8], gss[8];
    if (lane == 0) { gs[w_] = s; gss[w_] = ss; }
    __syncthreads();
    int wb = w_ & ~1;
    float S = gs[wb] + gs[wb + 1];
    float SS = gss[wb] + gss[wb + 1];
    float mu = S * (1.0f / 1024.0f);
    float var = SS * (1.0f / 1024.0f) - mu * mu;
    float inv = rsqrtf(var + 1e-5f);
    float* arow = af + (size_t)node * 1024;
    float vals[4][4] = {{v0.x, v0.y, v0.z, v0.w}, {v1.x, v1.y, v1.z, v1.w},
                        {v2.x, v2.y, v2.z, v2.w}, {a3.x, a3.y, a3.z, a3.w}};
#pragma unroll
    for (int r = 0; r < 4; r++) {
        int c = r * 256 + t * 4;
        float4 g4 = *(const float4*)(lg + c);
        float4 b4 = *(const float4*)(lb + c);
        float4 o4;
        o4.x = tf32r(gelu_f((vals[r][0] - mu) * inv * g4.x + b4.x));
        o4.y = tf32r(gelu_f((vals[r][1] - mu) * inv * g4.y + b4.y));
        o4.z = tf32r(gelu_f((vals[r][2] - mu) * inv * g4.z + b4.z));
        o4.w = tf32r(gelu_f((vals[r][3] - mu) * inv * g4.w + b4.w));
        *(float4*)(arow + c) = o4;
    }
}

// ---------------- LayerNorm(1024) + GELU -> af (layer 0) ---------------------
__global__ void k_ln(const float* __restrict__ h, const float* __restrict__ g,
                     const float* __restrict__ bta, float* __restrict__ af) {
    int node = blockIdx.x;
    int tid = threadIdx.x;
    const float* row = h + (size_t)node * 1024;
    float v[4];
    float s = 0.f, ss = 0.f;
#pragma unroll
    for (int i = 0; i < 4; i++) {
        v[i] = row[tid + i * 256];
        s += v[i]; ss += v[i] * v[i];
    }
    __shared__ float shs[8], shss[8];
#pragma unroll
    for (int o = 16; o; o >>= 1) {
        s += __shfl_down_sync(0xffffffffu, s, o);
        ss += __shfl_down_sync(0xffffffffu, ss, o);
    }
    int w = tid >> 5, lane = tid & 31;
    if (lane == 0) { shs[w] = s; shss[w] = ss; }
    __syncthreads();
    if (w == 0) {
        s = (lane < 8) ? shs[lane] : 0.f;
        ss = (lane < 8) ? shss[lane] : 0.f;
#pragma unroll
        for (int o = 4; o; o >>= 1) {
            s += __shfl_down_sync(0xffffffffu, s, o);
            ss += __shfl_down_sync(0xffffffffu, ss, o);
        }
        if (lane == 0) { shs[0] = s; shss[0] = ss; }
    }
    __syncthreads();
    float mu = shs[0] * (1.0f / 1024.0f);
    float var = shss[0] * (1.0f / 1024.0f) - mu * mu;
    float inv = rsqrtf(var + 1e-5f);
#pragma unroll
    for (int i = 0; i < 4; i++) {
        int c = tid + i * 256;
        float t = (v[i] - mu) * inv * g[c] + bta[c];
        af[(size_t)node * 1024 + c] = tf32r(gelu_f(t));
    }
}

// ---------------- final dot --------------------------------------------------
__global__ void k_out(const float* __restrict__ h2, const float* __restrict__ w3,
                      const float* __restrict__ b3, float* __restrict__ out, int n) {
    int gw = (blockIdx.x * blockDim.x + threadIdx.x) >> 5;
    int lane = threadIdx.x & 31;
    if (gw >= n) return;
    const float* row = h2 + (size_t)gw * 128;
    float s = 0.f;
#pragma unroll
    for (int i = 0; i < 4; i++) s += row[lane + i * 32] * w3[lane + i * 32];
#pragma unroll
    for (int o = 16; o; o >>= 1) s += __shfl_down_sync(0xffffffffu, s, o);
    if (lane == 0) out[gw] = s + b3[0];
}

// ---------------- host orchestration -----------------------------------------
template <typename T>
static T* sym(const void* s) {
    void* p = nullptr;
    cudaGetSymbolAddress(&p, s);
    return (T*)p;
}

extern "C" void kernel_launch(void* const* d_in, const int* in_sizes, int n_in,
                              void* d_out, int out_size) {
    const float* x      = (const float*)d_in[0];
    const int*   ei     = (const int*)d_in[1];
    const float* w_in   = (const float*)d_in[2];
    const float* b_in   = (const float*)d_in[3];
    const float* mh_w0  = (const float*)d_in[4];
    const float* mh_b0  = (const float*)d_in[5];
    const float* mh_w12 = (const float*)d_in[6];
    const float* mh_b12 = (const float*)d_in[7];
    const float* ln_g   = (const float*)d_in[8];
    const float* ln_b   = (const float*)d_in[9];
    const float* w1     = (const float*)d_in[10];
    const float* b1     = (const float*)d_in[11];
    const float* w2     = (const float*)d_in[12];
    const float* b2     = (const float*)d_in[13];
    const float* w3     = (const float*)d_in[14];
    const float* b3     = (const float*)d_in[15];
    float* out = (float*)d_out;

    float* cat  = sym<float>(g_cat);
    float* tmp  = sym<float>(g_tmp);
    float* u2   = sym<float>(g_u2);
    float* mlp  = sym<float>(g_mlp);
    float* mlp2 = sym<float>(g_mlp2);
    float* af   = sym<float>(g_af);
    float* wt   = sym<float>(g_wt);

    static cudaStream_t s1 = nullptr, s2 = nullptr;
    static cudaEvent_t ev[12];
    static bool init_done = false;
    if (!init_done) {
        cudaFuncSetAttribute(k_mma, cudaFuncAttributeMaxDynamicSharedMemorySize, 98304);
        cudaStreamCreateWithFlags(&s1, cudaStreamNonBlocking);
        cudaStreamCreateWithFlags(&s2, cudaStreamNonBlocking);
        for (int i = 0; i < 12; i++)
            cudaEventCreateWithFlags(&ev[i], cudaEventDisableTiming);
        init_done = true;
    }
    // ev idx: 0 fork, 1 big-wconv done, 2 input-proj done, 3/4/5 hops,
    //         6 L1 start, 7 L1 r0 done, 8 L2 start, 9 L2 r0 done

    const size_t OFF_L0 = 0, OFF_L1 = 262144, OFF_W1 = 2359296, OFF_W2 = 2621440;

    cudaEventRecord(ev[0], 0);
    cudaStreamWaitEvent(s1, ev[0], 0);
    cudaStreamWaitEvent(s2, ev[0], 0);

    // s1: CSR build, then L0 hops (dependencies are natural in-stream)
    k_zero<<<(NN + 255) / 256, 256, 0, s1>>>();
    k_count<<<(EE + 255) / 256, 256, 0, s1>>>(ei);
    k_dinvk<<<(NN + 255) / 256, 256, 0, s1>>>();
    k_scan<<<1, 1024, 0, s1>>>();
    k_scatter<<<(EE + 255) / 256, 256, 0, s1>>>(ei);

    // s2: big weight conversions
    k_wconv<<<dim3(1024, 8), 256, 0, s2>>>(mh_w12, wt + OFF_L1, 1024, 256, 262144, 262144);
    k_wconv<<<dim3(1024, 1), 256, 0, s2>>>(w1, wt + OFF_W1, 1024, 256, 262144, 262144);
    k_wconv<<<dim3(128, 1), 256, 0, s2>>>(w2, wt + OFF_W2, 256, 128, 32768, 32768);
    cudaEventRecord(ev[1], s2);

    // main: layer-0 weights + input projection -> af
    k_wconv<<<dim3(256, 4), 256>>>(mh_w0, wt + OFF_L0, 256, 256, 65536, 65536);
    k_gemm<2><<<dim3(4, (NN + 63) / 64), 256>>>(x, w_in, b_in, af, NN, 84, 256, 256);
    cudaEventRecord(ev[2], 0);

    float* t1 = tmp;
    float* t2 = tmp + (size_t)NN * 256;
    float* t3 = tmp + (size_t)2 * NN * 256;
    float* ua = tmp + (size_t)3 * NN * 256;
    const int SPG = NN / 4;

    // ---- layer 0: hops on s1, per-range GEMMs on main as hops complete ----
    cudaStreamWaitEvent(s1, ev[2], 0);
    {
        SpArgs p1{af, nullptr, nullptr, t1, nullptr, nullptr, nullptr, 256, 0, 0, 1};
        k_spmm<<<dim3(SPG, 1), 256, 0, s1>>>(p1);
        cudaEventRecord(ev[3], s1);
        SpArgs p2{t1, nullptr, nullptr, t2, nullptr, nullptr, nullptr, 256, 0, 0, 1};
        k_spmm<<<dim3(SPG, 1), 256, 0, s1>>>(p2);
        cudaEventRecord(ev[4], s1);
        SpArgs p3{t2, nullptr, nullptr, t3, nullptr, nullptr, nullptr, 256, 0, 0, 1};
        k_spmm<<<dim3(SPG, 1), 256, 0, s1>>>(p3);
        cudaEventRecord(ev[5], s1);

        GOut o;
        o.a[0] = af; o.a[1] = t1; o.a[2] = t2; o.a[3] = t3;
        o.p[0] = cat; o.p[1] = cat + 256; o.p[2] = cat + 512; o.p[3] = cat + 768;
        o.b[0] = mh_b0; o.b[1] = mh_b0 + 256; o.b[2] = mh_b0 + 512; o.b[3] = mh_b0 + 768;
        o.ld[0] = o.ld[1] = o.ld[2] = o.ld[3] = 1024;
        o.act = 0;
        k_mma<<<dim3(2, 79), 128, 98304>>>(wt + OFF_L0, o, 256, 0);  // range0 (af ready)
        cudaStreamWaitEvent(0, ev[3], 0);
        k_mma<<<dim3(2, 79), 128, 98304>>>(wt + OFF_L0, o, 256, 2);
        cudaStreamWaitEvent(0, ev[4], 0);
        k_mma<<<dim3(2, 79), 128, 98304>>>(wt + OFF_L0, o, 256, 4);
        cudaStreamWaitEvent(0, ev[5], 0);
        k_mma<<<dim3(2, 79), 128, 98304>>>(wt + OFF_L0, o, 256, 6);
        k_ln<<<NN, 256>>>(cat, ln_g, ln_b, af);
    }

    cudaStreamWaitEvent(0, ev[1], 0);   // big weights ready

    // ---- layers 1,2: range0 GEMM on s2 ∥ ranges1-3 + spmm on main ----
    auto LAYER = [&](size_t woff, const float* bb, const float* lg, const float* lb,
                     int evStart, int evR0) {
        GOut o;
        o.a[0] = o.a[1] = o.a[2] = o.a[3] = af;
        o.p[0] = cat; o.p[1] = t1; o.p[2] = t2; o.p[3] = t3;
        o.b[0] = bb;  o.b[1] = nullptr; o.b[2] = nullptr; o.b[3] = nullptr;
        o.ld[0] = 1024; o.ld[1] = 256; o.ld[2] = 256; o.ld[3] = 256;
        o.act = 0;
        cudaEventRecord(ev[evStart], 0);
        cudaStreamWaitEvent(s2, ev[evStart], 0);
        k_mma<<<dim3(2, 79), 128, 98304, s2>>>(wt + woff, o, 1024, 0);   // range0 -> cat
        cudaEventRecord(ev[evR0], s2);
        k_mma<<<dim3(6, 79), 128, 98304>>>(wt + woff, o, 1024, 2);       // ranges 1-3
        SpArgs h1{t1, t2, t3, cat + 256, ua, u2, bb + 256, 1024, 256, 256, 0};
        k_spmm<<<dim3(SPG, 3), 256>>>(h1);
        SpArgs h2a{ua, u2, nullptr, cat + 512, t1, nullptr, bb + 512, 1024, 256, 0, 0};
        k_spmm<<<dim3(SPG, 2), 256>>>(h2a);
        cudaStreamWaitEvent(0, ev[evR0], 0);
        k_spmm_ln<<<SPG, 256>>>(t1, cat, bb + 768, lg, lb, af);
    };

    LAYER(OFF_L1,              mh_b12,        ln_g + 1024, ln_b + 1024, 6, 7);
    LAYER(OFF_L1 + 4 * 262144, mh_b12 + 1024, ln_g + 2048, ln_b + 2048, 8, 9);

    // ---- head MLP ----
    GOut oh;
    oh.a[0] = af; oh.a[1] = oh.a[2] = oh.a[3] = nullptr;
    oh.p[0] = mlp; oh.p[1] = oh.p[2] = oh.p[3] = nullptr;
    oh.b[0] = b1;  oh.b[1] = oh.b[2] = oh.b[3] = nullptr;
    oh.ld[0] = 256; oh.ld[1] = oh.ld[2] = oh.ld[3] = 0;
    oh.act = 2;
    k_mma<<<dim3(2, 79), 128, 98304>>>(wt + OFF_W1, oh, 1024, 0);

    GOut o2;
    o2.a[0] = mlp; o2.a[1] = o2.a[2] = o2.a[3] = nullptr;
    o2.p[0] = mlp2; o2.p[1] = o2.p[2] = o2.p[3] = nullptr;
    o2.b[0] = b2;   o2.b[1] = o2.b[2] = o2.b[3] = nullptr;
    o2.ld[0] = 128; o2.ld[1] = o2.ld[2] = o2.ld[3] = 0;
    o2.act = 1;
    k_mma<<<dim3(1, 79), 128, 98304>>>(wt + OFF_W2, o2, 256, 0);

    k_out<<<(NN * 32 + 255) / 256, 256>>>(mlp2, w3, b3, out, NN);
}